// round 2
// baseline (speedup 1.0000x reference)
#include <cuda_runtime.h>
#include <math.h>

// Problem constants (shapes fixed by the dataset)
#define HC   128      // HEADS * C
#define CD   64       // C
#define FIN  128      // Fin of layer 1
#define NMAX 50048
#define EMAX 800256
#define ETMAX (NMAX + EMAX)

// ---------------- scratch (device globals; no allocation) ----------------
__device__ __align__(16) float  g_h[(size_t)NMAX * HC];     // GEMM output [N,128]
__device__ __align__(16) float  g_acc[(size_t)NMAX * CD];   // layer-1 aggr / layer-2 input
__device__ float    g_sdst[NMAX * 2];           // per-node dst-scores [N,H]
__device__ float    g_ssrc[NMAX * 2];           // per-node src-scores [N,H]
__device__ __align__(16) float2 g_alpha[ETMAX]; // per-edge alpha (raw, then exp)
__device__ unsigned g_maxEnc[2];                // order-encoded global max per layer
__device__ float    g_sum[4];                   // per-layer per-head sums
__device__ float    g_inv[4];                   // 0.5 / (sum + eps)
__device__ int      g_is32;                     // 1 if edge_index is int32, 0 if int64

// float <-> order-preserving uint for atomicMax
__device__ __forceinline__ unsigned encf(float f) {
    unsigned u = __float_as_uint(f);
    return (u & 0x80000000u) ? ~u : (u | 0x80000000u);
}
__device__ __forceinline__ float decf(unsigned u) {
    return (u & 0x80000000u) ? __uint_as_float(u & 0x7fffffffu)
                             : __uint_as_float(~u);
}

// unified edge accessor (handles int32 or int64 storage)
__device__ __forceinline__ void load_edge(const int* __restrict__ ei32,
                                          int e, int E, int& s, int& d) {
    if (g_is32) { s = ei32[e];     d = ei32[E + e]; }
    else        { s = ei32[2 * e]; d = ei32[2 * (E + e)]; }
}

// ---------------- dtype detection ----------------
// If edge_index is int64 (values < 2^31, nonneg), all odd 32-bit words are 0.
// If int32, odd words are random node indices -> OR over 64 samples is nonzero.
__global__ void detect_kernel(const int* __restrict__ ei32, int E) {
    int t = threadIdx.x;
    unsigned v = 0;
    if (t < 64 && t < E) v = (unsigned)ei32[2 * t + 1];
#pragma unroll
    for (int o = 16; o > 0; o >>= 1) v |= __shfl_xor_sync(0xffffffffu, v, o);
    __shared__ unsigned sh[2];
    if ((t & 31) == 0) sh[t >> 5] = v;
    __syncthreads();
    if (t == 0) g_is32 = ((sh[0] | sh[1]) != 0u) ? 1 : 0;
}

// ---------------- init: zero accumulators, output, scalars ----------------
__global__ void init_kernel(float* __restrict__ out, int n) {
    int i = blockIdx.x * blockDim.x + threadIdx.x;
    int stride = gridDim.x * blockDim.x;
    for (int j = i; j < n; j += stride) {
        g_acc[j] = 0.f;
        out[j]   = 0.f;
    }
    if (i < 2) g_maxEnc[i] = 0u;
    if (i < 4) g_sum[i] = 0.f;
}

// ---------------- GEMM: Hout[N,128] = X[N,K] @ W[128,K]^T ----------------
// 128-row x 128-col block tile, 8x8 register tile per thread, K chunked by 32.
#define GP 132  // padded smem pitch (floats)

template <int K>
__global__ void __launch_bounds__(256) gemm_kernel(
    const float* __restrict__ X0, int useAcc,
    const float* __restrict__ W, int N)
{
    __shared__ __align__(16) float sX[32 * GP];
    __shared__ __align__(16) float sW[32 * GP];

    const float* X = useAcc ? g_acc : X0;

    int t    = threadIdx.x;
    int row0 = blockIdx.x * 128;
    int tx   = t & 15;
    int ty   = t >> 4;

    float acc[8][8];
#pragma unroll
    for (int i = 0; i < 8; i++)
#pragma unroll
        for (int j = 0; j < 8; j++) acc[i][j] = 0.f;

    for (int kc = 0; kc < K; kc += 32) {
        // cooperative transpose-load of X chunk and W chunk into smem
#pragma unroll
        for (int it = 0; it < 4; it++) {
            int idx = t + it * 256;
            int r = idx >> 3;        // row (X) / output-dim m (W), 0..127
            int j = idx & 7;         // k-quad within chunk
            int k = 4 * j;

            float4 v = make_float4(0.f, 0.f, 0.f, 0.f);
            int grow = row0 + r;
            if (grow < N)
                v = *reinterpret_cast<const float4*>(X + (size_t)grow * K + kc + k);
            sX[(k + 0) * GP + r] = v.x;
            sX[(k + 1) * GP + r] = v.y;
            sX[(k + 2) * GP + r] = v.z;
            sX[(k + 3) * GP + r] = v.w;

            float4 w = *reinterpret_cast<const float4*>(W + (size_t)r * K + kc + k);
            sW[(k + 0) * GP + r] = w.x;
            sW[(k + 1) * GP + r] = w.y;
            sW[(k + 2) * GP + r] = w.z;
            sW[(k + 3) * GP + r] = w.w;
        }
        __syncthreads();

#pragma unroll 4
        for (int k = 0; k < 32; k++) {
            float4 a0 = *reinterpret_cast<const float4*>(&sX[k * GP + ty * 8]);
            float4 a1 = *reinterpret_cast<const float4*>(&sX[k * GP + ty * 8 + 4]);
            float4 b0 = *reinterpret_cast<const float4*>(&sW[k * GP + tx * 8]);
            float4 b1 = *reinterpret_cast<const float4*>(&sW[k * GP + tx * 8 + 4]);
            float a[8] = {a0.x, a0.y, a0.z, a0.w, a1.x, a1.y, a1.z, a1.w};
            float b[8] = {b0.x, b0.y, b0.z, b0.w, b1.x, b1.y, b1.z, b1.w};
#pragma unroll
            for (int i = 0; i < 8; i++)
#pragma unroll
                for (int j = 0; j < 8; j++)
                    acc[i][j] = fmaf(a[i], b[j], acc[i][j]);
        }
        __syncthreads();
    }

#pragma unroll
    for (int i = 0; i < 8; i++) {
        int grow = row0 + ty * 8 + i;
        if (grow < N) {
            float4 o0 = make_float4(acc[i][0], acc[i][1], acc[i][2], acc[i][3]);
            float4 o1 = make_float4(acc[i][4], acc[i][5], acc[i][6], acc[i][7]);
            float* dst = g_h + (size_t)grow * HC + tx * 8;
            *reinterpret_cast<float4*>(dst)     = o0;
            *reinterpret_cast<float4*>(dst + 4) = o1;
        }
    }
}

// ---------------- per-node attention scores ----------------
// s_dst[n,h] = dot(h[n,h,:], att[h, 0:64]);  s_src[n,h] = dot(h[n,h,:], att[h, 64:128])
__global__ void __launch_bounds__(256) score_kernel(const float* __restrict__ att, int N)
{
    __shared__ float sAtt[256];
    int t = threadIdx.x;
    if (t < 256) sAtt[t] = att[t];
    __syncthreads();

    int node = blockIdx.x * 8 + (t >> 5);
    int l = t & 31;
    if (node >= N) return;

    const float* hr = g_h + (size_t)node * HC;
    float h0 = hr[l], h1 = hr[32 + l], h2 = hr[64 + l], h3 = hr[96 + l];

    float d0 = h0 * sAtt[l]       + h1 * sAtt[32 + l];
    float s0 = h0 * sAtt[64 + l]  + h1 * sAtt[96 + l];
    float d1 = h2 * sAtt[128 + l] + h3 * sAtt[160 + l];
    float s1 = h2 * sAtt[192 + l] + h3 * sAtt[224 + l];

#pragma unroll
    for (int o = 16; o > 0; o >>= 1) {
        d0 += __shfl_xor_sync(0xffffffffu, d0, o);
        s0 += __shfl_xor_sync(0xffffffffu, s0, o);
        d1 += __shfl_xor_sync(0xffffffffu, d1, o);
        s1 += __shfl_xor_sync(0xffffffffu, s1, o);
    }
    if (l == 0) {
        g_sdst[node * 2]     = d0;
        g_sdst[node * 2 + 1] = d1;
        g_ssrc[node * 2]     = s0;
        g_ssrc[node * 2 + 1] = s1;
    }
}

// ---------------- per-edge raw alpha + leaky relu + global max ----------------
__global__ void __launch_bounds__(256) alpha_kernel(
    const int* __restrict__ ei32, int E, int N, int layer)
{
    int e  = blockIdx.x * blockDim.x + threadIdx.x;
    int ET = E + N;
    float m = -INFINITY;
    if (e < ET) {
        int s, d;
        if (e < E) load_edge(ei32, e, E, s, d);
        else       s = d = e - E;
        float a0 = g_sdst[d * 2]     + g_ssrc[s * 2];
        float a1 = g_sdst[d * 2 + 1] + g_ssrc[s * 2 + 1];
        a0 = (a0 >= 0.f) ? a0 : 0.2f * a0;
        a1 = (a1 >= 0.f) ? a1 : 0.2f * a1;
        g_alpha[e] = make_float2(a0, a1);
        m = fmaxf(a0, a1);
    }
#pragma unroll
    for (int o = 16; o > 0; o >>= 1)
        m = fmaxf(m, __shfl_xor_sync(0xffffffffu, m, o));
    __shared__ float sm[8];
    if ((threadIdx.x & 31) == 0) sm[threadIdx.x >> 5] = m;
    __syncthreads();
    if (threadIdx.x == 0) {
        float bm = sm[0];
#pragma unroll
        for (int i = 1; i < 8; i++) bm = fmaxf(bm, sm[i]);
        atomicMax(&g_maxEnc[layer], encf(bm));
    }
}

// ---------------- exp(alpha - max), per-head sums ----------------
__global__ void __launch_bounds__(256) sumexp_kernel(int E, int N, int layer)
{
    int e  = blockIdx.x * blockDim.x + threadIdx.x;
    int ET = E + N;
    float s0 = 0.f, s1 = 0.f;
    if (e < ET) {
        float mx = decf(g_maxEnc[layer]);
        float2 a = g_alpha[e];
        s0 = expf(a.x - mx);
        s1 = expf(a.y - mx);
        g_alpha[e] = make_float2(s0, s1);
    }
#pragma unroll
    for (int o = 16; o > 0; o >>= 1) {
        s0 += __shfl_xor_sync(0xffffffffu, s0, o);
        s1 += __shfl_xor_sync(0xffffffffu, s1, o);
    }
    __shared__ float sm0[8], sm1[8];
    if ((threadIdx.x & 31) == 0) {
        sm0[threadIdx.x >> 5] = s0;
        sm1[threadIdx.x >> 5] = s1;
    }
    __syncthreads();
    if (threadIdx.x == 0) {
        float t0 = 0.f, t1 = 0.f;
#pragma unroll
        for (int i = 0; i < 8; i++) { t0 += sm0[i]; t1 += sm1[i]; }
        atomicAdd(&g_sum[layer * 2],     t0);
        atomicAdd(&g_sum[layer * 2 + 1], t1);
    }
}

__global__ void finalize_sums(int layer)
{
    if (threadIdx.x < 2) {
        int i = layer * 2 + threadIdx.x;
        g_inv[i] = 0.5f / (g_sum[i] + 1e-10f);   // 0.5 = mean over 2 heads
    }
}

// ---------------- aggregation: out[dst] += sum_h w_h * h[src,h,:] ----------------
// 16 threads per edge, float4 per thread per head.
__global__ void __launch_bounds__(256) aggregate_kernel(
    const int* __restrict__ ei32, int E, int N, int layer,
    float* __restrict__ outp, int useAcc)
{
    int gid = blockIdx.x * blockDim.x + threadIdx.x;
    int e = gid >> 4;
    int g = gid & 15;
    int ET = E + N;
    if (e >= ET) return;

    int s, d;
    if (e < E) load_edge(ei32, e, E, s, d);
    else       s = d = e - E;

    float2 a = g_alpha[e];
    float w0 = a.x * g_inv[layer * 2];
    float w1 = a.y * g_inv[layer * 2 + 1];

    const float4* hv = reinterpret_cast<const float4*>(g_h);
    float4 v0 = hv[(size_t)s * 32 + g];        // head 0, channels 4g..4g+3
    float4 v1 = hv[(size_t)s * 32 + 16 + g];   // head 1

    float mx = w0 * v0.x + w1 * v1.x;
    float my = w0 * v0.y + w1 * v1.y;
    float mz = w0 * v0.z + w1 * v1.z;
    float mw = w0 * v0.w + w1 * v1.w;

    float* o = (useAcc ? g_acc : outp) + (size_t)d * CD + g * 4;
    atomicAdd(o + 0, mx);
    atomicAdd(o + 1, my);
    atomicAdd(o + 2, mz);
    atomicAdd(o + 3, mw);
}

// ---------------- epilogues ----------------
__global__ void relu_bias_kernel(const float* __restrict__ b, int n)
{
    int i = blockIdx.x * blockDim.x + threadIdx.x;
    if (i < n) g_acc[i] = fmaxf(g_acc[i] + b[i & 63], 0.f);
}

__global__ void bias_add_kernel(float* __restrict__ out, const float* __restrict__ b, int n)
{
    int i = blockIdx.x * blockDim.x + threadIdx.x;
    if (i < n) out[i] += b[i & 63];
}

// ---------------- launch ----------------
extern "C" void kernel_launch(void* const* d_in, const int* in_sizes, int n_in,
                              void* d_out, int out_size)
{
    const float* x    = (const float*)d_in[0];
    const int*   ei32 = (const int*)d_in[1];
    const float* W1   = (const float*)d_in[2];
    const float* att1 = (const float*)d_in[3];
    const float* b1   = (const float*)d_in[4];
    const float* W2   = (const float*)d_in[5];
    const float* att2 = (const float*)d_in[6];
    const float* b2   = (const float*)d_in[7];
    float* out = (float*)d_out;

    int N  = in_sizes[0] / FIN;   // x: [N, 128]
    int E  = in_sizes[1] / 2;     // edge_index: [2, E]
    int ET = E + N;

    int nOut = N * CD;

    detect_kernel<<<1, 64>>>(ei32, E);
    init_kernel<<<(nOut + 255) / 256, 256>>>(out, nOut);

    // ---- layer 1 ----
    gemm_kernel<FIN><<<(N + 127) / 128, 256>>>(x, 0, W1, N);
    score_kernel<<<(N + 7) / 8, 256>>>(att1, N);
    alpha_kernel<<<(ET + 255) / 256, 256>>>(ei32, E, N, 0);
    sumexp_kernel<<<(ET + 255) / 256, 256>>>(E, N, 0);
    finalize_sums<<<1, 32>>>(0);
    aggregate_kernel<<<(ET * 16 + 255) / 256, 256>>>(ei32, E, N, 0, out, 1);
    relu_bias_kernel<<<(nOut + 255) / 256, 256>>>(b1, nOut);

    // ---- layer 2 ----
    gemm_kernel<CD><<<(N + 127) / 128, 256>>>(x /*unused*/, 1, W2, N);
    score_kernel<<<(N + 7) / 8, 256>>>(att2, N);
    alpha_kernel<<<(ET + 255) / 256, 256>>>(ei32, E, N, 1);
    sumexp_kernel<<<(ET + 255) / 256, 256>>>(E, N, 1);
    finalize_sums<<<1, 32>>>(1);
    aggregate_kernel<<<(ET * 16 + 255) / 256, 256>>>(ei32, E, N, 1, out, 0);
    bias_add_kernel<<<(nOut + 255) / 256, 256>>>(out, b2, nOut);
}

// round 3
// speedup vs baseline: 1.2846x; 1.2846x over previous
#include <cuda_runtime.h>
#include <math.h>

// Problem constants (shapes fixed by the dataset)
#define HC   128      // HEADS * C
#define CD   64       // C
#define FIN  128      // Fin of layer 1
#define NMAX 50048
#define EMAX 800256
#define ETMAX (NMAX + EMAX)

// ---------------- scratch (device globals; no allocation) ----------------
__device__ __align__(16) float  g_h[(size_t)NMAX * HC];     // GEMM output [N,128]
__device__ __align__(16) float  g_acc[(size_t)NMAX * CD];   // layer-1 out / layer-2 input
__device__ float    g_sdst[NMAX * 2];           // per-node dst-scores [N,H]
__device__ float    g_ssrc[NMAX * 2];           // per-node src-scores [N,H]
__device__ __align__(16) float2 g_alpha[ETMAX]; // per-edge alpha (raw, then exp)
__device__ unsigned g_maxEnc[2];                // order-encoded global max per layer
__device__ float    g_sum[4];                   // per-layer per-head sums
__device__ float    g_inv[4];                   // 0.5 / (sum + eps)
__device__ int      g_is32;                     // 1 if edge_index is int32
// CSR (built once per launch; edges identical for both layers)
__device__ int      g_deg[NMAX];
__device__ int      g_roff[NMAX + 1];
__device__ int      g_cursor[NMAX];
__device__ __align__(8) int2 g_csr[ETMAX];      // (src, edge-id) per incoming edge

// float <-> order-preserving uint for atomicMax
__device__ __forceinline__ unsigned encf(float f) {
    unsigned u = __float_as_uint(f);
    return (u & 0x80000000u) ? ~u : (u | 0x80000000u);
}
__device__ __forceinline__ float decf(unsigned u) {
    return (u & 0x80000000u) ? __uint_as_float(u & 0x7fffffffu)
                             : __uint_as_float(~u);
}

// unified edge accessor (handles int32 or int64 storage)
__device__ __forceinline__ void load_edge(const int* __restrict__ ei32,
                                          int e, int E, int& s, int& d) {
    if (g_is32) { s = ei32[e];     d = ei32[E + e]; }
    else        { s = ei32[2 * e]; d = ei32[2 * (E + e)]; }
}

// ---------------- dtype detection ----------------
__global__ void detect_kernel(const int* __restrict__ ei32, int E) {
    int t = threadIdx.x;
    unsigned v = 0;
    if (t < 64 && t < E) v = (unsigned)ei32[2 * t + 1];
#pragma unroll
    for (int o = 16; o > 0; o >>= 1) v |= __shfl_xor_sync(0xffffffffu, v, o);
    __shared__ unsigned sh[2];
    if ((t & 31) == 0) sh[t >> 5] = v;
    __syncthreads();
    if (t == 0) g_is32 = ((sh[0] | sh[1]) != 0u) ? 1 : 0;
}

// ---------------- init: deg=1 (self loop), scalars ----------------
__global__ void init_kernel(int N) {
    int i = blockIdx.x * blockDim.x + threadIdx.x;
    if (i < N) g_deg[i] = 1;
    if (i < 2) g_maxEnc[i] = 0u;
    if (i < 4) g_sum[i] = 0.f;
}

// ---------------- CSR build ----------------
__global__ void hist_kernel(const int* __restrict__ ei32, int E) {
    int e = blockIdx.x * blockDim.x + threadIdx.x;
    if (e < E) {
        int s, d;
        load_edge(ei32, e, E, s, d);
        atomicAdd(&g_deg[d], 1);
    }
}

// single-block exclusive scan of g_deg -> g_roff, g_cursor
__global__ void scan_kernel(int N) {
    __shared__ int sPart[1024];
    int t = threadIdx.x;
    int per = (N + 1023) / 1024;
    int beg = t * per;
    int end = min(beg + per, N);
    int sum = 0;
    for (int i = beg; i < end; i++) sum += g_deg[i];
    sPart[t] = sum;
    __syncthreads();
    for (int off = 1; off < 1024; off <<= 1) {
        int v = (t >= off) ? sPart[t - off] : 0;
        __syncthreads();
        sPart[t] += v;
        __syncthreads();
    }
    int excl = (t == 0) ? 0 : sPart[t - 1];
    for (int i = beg; i < end; i++) {
        int dg = g_deg[i];
        g_roff[i] = excl;
        g_cursor[i] = excl;
        excl += dg;
    }
    if (t == 1023) g_roff[N] = sPart[1023];
}

__global__ void scatter_kernel(const int* __restrict__ ei32, int E, int N) {
    int e = blockIdx.x * blockDim.x + threadIdx.x;
    int ET = E + N;
    if (e >= ET) return;
    int s, d;
    if (e < E) load_edge(ei32, e, E, s, d);
    else       s = d = e - E;
    int pos = atomicAdd(&g_cursor[d], 1);
    g_csr[pos] = make_int2(s, e);
}

// ---------------- GEMM: Hout[N,128] = X[N,K] @ W[128,K]^T (+ fused scores) ----
#define GP 132  // padded smem pitch (floats)

template <int K>
__global__ void __launch_bounds__(256) gemm_kernel(
    const float* __restrict__ X0, int useAcc,
    const float* __restrict__ W, const float* __restrict__ att, int N)
{
    __shared__ __align__(16) float sX[32 * GP];
    __shared__ __align__(16) float sW[32 * GP];
    __shared__ float sAtt[256];

    const float* X = useAcc ? g_acc : X0;

    int t    = threadIdx.x;
    int row0 = blockIdx.x * 128;
    int tx   = t & 15;
    int ty   = t >> 4;
    int lane = t & 31;

    if (t < 256) sAtt[t] = att[t];

    float acc[8][8];
#pragma unroll
    for (int i = 0; i < 8; i++)
#pragma unroll
        for (int j = 0; j < 8; j++) acc[i][j] = 0.f;

    for (int kc = 0; kc < K; kc += 32) {
#pragma unroll
        for (int it = 0; it < 4; it++) {
            int idx = t + it * 256;
            int r = idx >> 3;
            int j = idx & 7;
            int k = 4 * j;

            float4 v = make_float4(0.f, 0.f, 0.f, 0.f);
            int grow = row0 + r;
            if (grow < N)
                v = *reinterpret_cast<const float4*>(X + (size_t)grow * K + kc + k);
            sX[(k + 0) * GP + r] = v.x;
            sX[(k + 1) * GP + r] = v.y;
            sX[(k + 2) * GP + r] = v.z;
            sX[(k + 3) * GP + r] = v.w;

            float4 w = *reinterpret_cast<const float4*>(W + (size_t)r * K + kc + k);
            sW[(k + 0) * GP + r] = w.x;
            sW[(k + 1) * GP + r] = w.y;
            sW[(k + 2) * GP + r] = w.z;
            sW[(k + 3) * GP + r] = w.w;
        }
        __syncthreads();

#pragma unroll 4
        for (int k = 0; k < 32; k++) {
            float4 a0 = *reinterpret_cast<const float4*>(&sX[k * GP + ty * 8]);
            float4 a1 = *reinterpret_cast<const float4*>(&sX[k * GP + ty * 8 + 4]);
            float4 b0 = *reinterpret_cast<const float4*>(&sW[k * GP + tx * 8]);
            float4 b1 = *reinterpret_cast<const float4*>(&sW[k * GP + tx * 8 + 4]);
            float a[8] = {a0.x, a0.y, a0.z, a0.w, a1.x, a1.y, a1.z, a1.w};
            float b[8] = {b0.x, b0.y, b0.z, b0.w, b1.x, b1.y, b1.z, b1.w};
#pragma unroll
            for (int i = 0; i < 8; i++)
#pragma unroll
                for (int j = 0; j < 8; j++)
                    acc[i][j] = fmaf(a[i], b[j], acc[i][j]);
        }
        __syncthreads();
    }

#pragma unroll
    for (int i = 0; i < 8; i++) {
        int grow = row0 + ty * 8 + i;
        if (grow < N) {
            float4 o0 = make_float4(acc[i][0], acc[i][1], acc[i][2], acc[i][3]);
            float4 o1 = make_float4(acc[i][4], acc[i][5], acc[i][6], acc[i][7]);
            float* dst = g_h + (size_t)grow * HC + tx * 8;
            *reinterpret_cast<float4*>(dst)     = o0;
            *reinterpret_cast<float4*>(dst + 4) = o1;
        }
        float dp = 0.f, sp = 0.f;
#pragma unroll
        for (int j = 0; j < 8; j++) {
            int g = tx * 8 + j;
            int base = (g >> 6) * 128 + (g & 63);
            dp = fmaf(acc[i][j], sAtt[base], dp);
            sp = fmaf(acc[i][j], sAtt[base + 64], sp);
        }
#pragma unroll
        for (int o = 4; o > 0; o >>= 1) {
            dp += __shfl_xor_sync(0xffffffffu, dp, o);
            sp += __shfl_xor_sync(0xffffffffu, sp, o);
        }
        if ((lane & 7) == 0 && grow < N) {
            int h = (lane >> 3) & 1;
            g_sdst[grow * 2 + h] = dp;
            g_ssrc[grow * 2 + h] = sp;
        }
    }
}

// ---------------- per-edge raw alpha + leaky relu + global max ----------------
__global__ void __launch_bounds__(256) alpha_kernel(
    const int* __restrict__ ei32, int E, int N, int layer)
{
    int e  = blockIdx.x * blockDim.x + threadIdx.x;
    int ET = E + N;
    float m = -INFINITY;
    if (e < ET) {
        int s, d;
        if (e < E) load_edge(ei32, e, E, s, d);
        else       s = d = e - E;
        float a0 = g_sdst[d * 2]     + g_ssrc[s * 2];
        float a1 = g_sdst[d * 2 + 1] + g_ssrc[s * 2 + 1];
        a0 = (a0 >= 0.f) ? a0 : 0.2f * a0;
        a1 = (a1 >= 0.f) ? a1 : 0.2f * a1;
        g_alpha[e] = make_float2(a0, a1);
        m = fmaxf(a0, a1);
    }
#pragma unroll
    for (int o = 16; o > 0; o >>= 1)
        m = fmaxf(m, __shfl_xor_sync(0xffffffffu, m, o));
    __shared__ float sm[8];
    if ((threadIdx.x & 31) == 0) sm[threadIdx.x >> 5] = m;
    __syncthreads();
    if (threadIdx.x == 0) {
        float bm = sm[0];
#pragma unroll
        for (int i = 1; i < 8; i++) bm = fmaxf(bm, sm[i]);
        atomicMax(&g_maxEnc[layer], encf(bm));
    }
}

// ---------------- exp(alpha - max), per-head sums ----------------
__global__ void __launch_bounds__(256) sumexp_kernel(int E, int N, int layer)
{
    int e  = blockIdx.x * blockDim.x + threadIdx.x;
    int ET = E + N;
    float s0 = 0.f, s1 = 0.f;
    if (e < ET) {
        float mx = decf(g_maxEnc[layer]);
        float2 a = g_alpha[e];
        s0 = __expf(a.x - mx);
        s1 = __expf(a.y - mx);
        g_alpha[e] = make_float2(s0, s1);
    }
#pragma unroll
    for (int o = 16; o > 0; o >>= 1) {
        s0 += __shfl_xor_sync(0xffffffffu, s0, o);
        s1 += __shfl_xor_sync(0xffffffffu, s1, o);
    }
    __shared__ float sm0[8], sm1[8];
    if ((threadIdx.x & 31) == 0) {
        sm0[threadIdx.x >> 5] = s0;
        sm1[threadIdx.x >> 5] = s1;
    }
    __syncthreads();
    if (threadIdx.x == 0) {
        float t0 = 0.f, t1 = 0.f;
#pragma unroll
        for (int i = 0; i < 8; i++) { t0 += sm0[i]; t1 += sm1[i]; }
        atomicAdd(&g_sum[layer * 2],     t0);
        atomicAdd(&g_sum[layer * 2 + 1], t1);
    }
}

__global__ void finalize_sums(int layer)
{
    if (threadIdx.x < 2) {
        int i = layer * 2 + threadIdx.x;
        g_inv[i] = 0.5f / (g_sum[i] + 1e-10f);   // 0.5 = mean over 2 heads
    }
}

// ---------------- gather aggregation: one warp per dst node, no atomics ------
__global__ void __launch_bounds__(256) gather_kernel(
    int N, int layer, float* __restrict__ outp0,
    const float* __restrict__ bias, int doRelu, int toAcc)
{
    int wid  = (blockIdx.x * blockDim.x + threadIdx.x) >> 5;
    int lane = threadIdx.x & 31;
    if (wid >= N) return;
    int d = wid;

    float* outp = toAcc ? g_acc : outp0;

    int beg = g_roff[d];
    int end = g_roff[d + 1];

    float inv0 = g_inv[layer * 2];
    float inv1 = g_inv[layer * 2 + 1];

    const float4* hv = reinterpret_cast<const float4*>(g_h);
    float4 acc = make_float4(0.f, 0.f, 0.f, 0.f);

    for (int base = beg; base < end; base += 32) {
        int idx = base + lane;
        int2  se = make_int2(0, 0);
        float aw0 = 0.f, aw1 = 0.f;
        if (idx < end) {
            se = g_csr[idx];
            float2 al = g_alpha[se.y];
            aw0 = al.x * inv0;
            aw1 = al.y * inv1;
        }
        int cnt = min(32, end - base);
#pragma unroll 4
        for (int j = 0; j < cnt; j++) {
            int   s  = __shfl_sync(0xffffffffu, se.x, j);
            float w0 = __shfl_sync(0xffffffffu, aw0, j);
            float w1 = __shfl_sync(0xffffffffu, aw1, j);
            float ww = (lane < 16) ? w0 : w1;
            float4 v = hv[(size_t)s * 32 + lane];
            acc.x = fmaf(ww, v.x, acc.x);
            acc.y = fmaf(ww, v.y, acc.y);
            acc.z = fmaf(ww, v.z, acc.z);
            acc.w = fmaf(ww, v.w, acc.w);
        }
    }

    acc.x += __shfl_xor_sync(0xffffffffu, acc.x, 16);
    acc.y += __shfl_xor_sync(0xffffffffu, acc.y, 16);
    acc.z += __shfl_xor_sync(0xffffffffu, acc.z, 16);
    acc.w += __shfl_xor_sync(0xffffffffu, acc.w, 16);

    if (lane < 16) {
        const float4 b = reinterpret_cast<const float4*>(bias)[lane];
        acc.x += b.x; acc.y += b.y; acc.z += b.z; acc.w += b.w;
        if (doRelu) {
            acc.x = fmaxf(acc.x, 0.f);
            acc.y = fmaxf(acc.y, 0.f);
            acc.z = fmaxf(acc.z, 0.f);
            acc.w = fmaxf(acc.w, 0.f);
        }
        reinterpret_cast<float4*>(outp + (size_t)d * CD)[lane] = acc;
    }
}

// ---------------- launch ----------------
extern "C" void kernel_launch(void* const* d_in, const int* in_sizes, int n_in,
                              void* d_out, int out_size)
{
    const float* x    = (const float*)d_in[0];
    const int*   ei32 = (const int*)d_in[1];
    const float* W1   = (const float*)d_in[2];
    const float* att1 = (const float*)d_in[3];
    const float* b1   = (const float*)d_in[4];
    const float* W2   = (const float*)d_in[5];
    const float* att2 = (const float*)d_in[6];
    const float* b2   = (const float*)d_in[7];
    float* out = (float*)d_out;

    int N  = in_sizes[0] / FIN;
    int E  = in_sizes[1] / 2;
    int ET = E + N;

    detect_kernel<<<1, 64>>>(ei32, E);
    init_kernel<<<(N + 255) / 256, 256>>>(N);
    hist_kernel<<<(E + 255) / 256, 256>>>(ei32, E);
    scan_kernel<<<1, 1024>>>(N);
    scatter_kernel<<<(ET + 255) / 256, 256>>>(ei32, E, N);

    // ---- layer 1 ----
    gemm_kernel<FIN><<<(N + 127) / 128, 256>>>(x, 0, W1, att1, N);
    alpha_kernel<<<(ET + 255) / 256, 256>>>(ei32, E, N, 0);
    sumexp_kernel<<<(ET + 255) / 256, 256>>>(E, N, 0);
    finalize_sums<<<1, 32>>>(0);
    gather_kernel<<<(N * 32 + 255) / 256, 256>>>(N, 0, out, b1, 1, 1);

    // ---- layer 2 ----
    gemm_kernel<CD><<<(N + 127) / 128, 256>>>(x /*unused*/, 1, W2, att2, N);
    alpha_kernel<<<(ET + 255) / 256, 256>>>(ei32, E, N, 1);
    sumexp_kernel<<<(ET + 255) / 256, 256>>>(E, N, 1);
    finalize_sums<<<1, 32>>>(1);
    gather_kernel<<<(N * 32 + 255) / 256, 256>>>(N, 1, out, b2, 0, 0);
}

// round 4
// speedup vs baseline: 1.6757x; 1.3045x over previous
#include <cuda_runtime.h>
#include <math.h>

// Problem constants (shapes fixed by the dataset)
#define HC   128      // HEADS * C
#define CD   64       // C
#define FIN  128      // Fin of layer 1
#define NMAX 50048
#define EMAX 800256
#define ETMAX (NMAX + EMAX)
#define SCAN_CHUNK 2048   // elements per scan block (256 thr x 8)

// ---------------- scratch (device globals; no allocation) ----------------
__device__ __align__(16) float  g_h[(size_t)NMAX * HC];     // GEMM output [N,128]
__device__ __align__(16) float  g_acc[(size_t)NMAX * CD];   // layer-1 out / layer-2 input
__device__ float    g_sdst[NMAX * 2];           // per-node dst-scores [N,H]
__device__ float    g_ssrc[NMAX * 2];           // per-node src-scores [N,H]
__device__ __align__(16) float2 g_alpha[ETMAX]; // per-edge alpha (raw, then exp)
__device__ unsigned g_maxEnc[2];                // order-encoded global max per layer
__device__ float    g_sum[4];                   // per-layer per-head sums
__device__ float    g_inv[4];                   // 0.5 / (sum + eps)
__device__ int      g_is32;                     // 1 if edge_index is int32
// CSR (built once per launch; edges identical for both layers)
__device__ int      g_deg[NMAX];
__device__ int      g_roff[NMAX + 1];
__device__ int      g_cursor[NMAX];
__device__ __align__(8) int2 g_csr[ETMAX];      // (src, edge-id) per incoming edge
__device__ int      g_bsum[256];                // per-block degree sums
__device__ int      g_bbase[256];               // exclusive-scanned block bases

// float <-> order-preserving uint for atomicMax
__device__ __forceinline__ unsigned encf(float f) {
    unsigned u = __float_as_uint(f);
    return (u & 0x80000000u) ? ~u : (u | 0x80000000u);
}
__device__ __forceinline__ float decf(unsigned u) {
    return (u & 0x80000000u) ? __uint_as_float(u & 0x7fffffffu)
                             : __uint_as_float(~u);
}

// unified edge accessor (handles int32 or int64 storage)
__device__ __forceinline__ void load_edge(const int* __restrict__ ei32,
                                          int e, int E, int& s, int& d) {
    if (g_is32) { s = ei32[e];     d = ei32[E + e]; }
    else        { s = ei32[2 * e]; d = ei32[2 * (E + e)]; }
}

// ---------------- dtype detection ----------------
__global__ void detect_kernel(const int* __restrict__ ei32, int E) {
    int t = threadIdx.x;
    unsigned v = 0;
    if (t < 64 && t < E) v = (unsigned)ei32[2 * t + 1];
#pragma unroll
    for (int o = 16; o > 0; o >>= 1) v |= __shfl_xor_sync(0xffffffffu, v, o);
    __shared__ unsigned sh[2];
    if ((t & 31) == 0) sh[t >> 5] = v;
    __syncthreads();
    if (t == 0) g_is32 = ((sh[0] | sh[1]) != 0u) ? 1 : 0;
}

// ---------------- init: deg=1 (self loop), scalars ----------------
__global__ void init_kernel(int N) {
    int i = blockIdx.x * blockDim.x + threadIdx.x;
    if (i < N) g_deg[i] = 1;
    if (i < 2) g_maxEnc[i] = 0u;
    if (i < 4) g_sum[i] = 0.f;
}

// ---------------- CSR build ----------------
__global__ void hist_kernel(const int* __restrict__ ei32, int E) {
    int e = blockIdx.x * blockDim.x + threadIdx.x;
    if (e < E) {
        int s, d;
        load_edge(ei32, e, E, s, d);
        atomicAdd(&g_deg[d], 1);
    }
}

// phase 1: per-block sums of 2048 degrees
__global__ void __launch_bounds__(256) partial_kernel(int N) {
    __shared__ int sT[256];
    int b = blockIdx.x, t = threadIdx.x;
    int beg = b * SCAN_CHUNK + t * 8;
    int s = 0;
#pragma unroll
    for (int i = 0; i < 8; i++) {
        int idx = beg + i;
        if (idx < N) s += g_deg[idx];
    }
    sT[t] = s;
    __syncthreads();
#pragma unroll
    for (int off = 128; off > 0; off >>= 1) {
        if (t < off) sT[t] += sT[t + off];
        __syncthreads();
    }
    if (t == 0) g_bsum[b] = sT[0];
}

// phase 2: single block scans <=256 block sums
__global__ void scanp_kernel(int nb, int N) {
    __shared__ int sT[256];
    int t = threadIdx.x;
    sT[t] = (t < nb) ? g_bsum[t] : 0;
    __syncthreads();
    for (int off = 1; off < 256; off <<= 1) {
        int v = (t >= off) ? sT[t - off] : 0;
        __syncthreads();
        sT[t] += v;
        __syncthreads();
    }
    if (t < nb) g_bbase[t] = (t == 0) ? 0 : sT[t - 1];
    if (t == 0) g_roff[N] = sT[255];
}

// phase 3: per-block rescan + write roff/cursor
__global__ void __launch_bounds__(256) offsets_kernel(int N) {
    __shared__ int sT[256];
    int b = blockIdx.x, t = threadIdx.x;
    int beg = b * SCAN_CHUNK + t * 8;
    int v[8];
    int s = 0;
#pragma unroll
    for (int i = 0; i < 8; i++) {
        int idx = beg + i;
        v[i] = (idx < N) ? g_deg[idx] : 0;
        s += v[i];
    }
    sT[t] = s;
    __syncthreads();
    for (int off = 1; off < 256; off <<= 1) {
        int x = (t >= off) ? sT[t - off] : 0;
        __syncthreads();
        sT[t] += x;
        __syncthreads();
    }
    int excl = ((t == 0) ? 0 : sT[t - 1]) + g_bbase[b];
#pragma unroll
    for (int i = 0; i < 8; i++) {
        int idx = beg + i;
        if (idx < N) {
            g_roff[idx]   = excl;
            g_cursor[idx] = excl;
            excl += v[i];
        }
    }
}

__global__ void scatter_kernel(const int* __restrict__ ei32, int E, int N) {
    int e = blockIdx.x * blockDim.x + threadIdx.x;
    int ET = E + N;
    if (e >= ET) return;
    int s, d;
    if (e < E) load_edge(ei32, e, E, s, d);
    else       s = d = e - E;
    int pos = atomicAdd(&g_cursor[d], 1);
    g_csr[pos] = make_int2(s, e);
}

// ---------------- GEMM: Hout[N,128] = X[N,K] @ W[128,K]^T (+ fused scores) ----
#define GP 132  // padded smem pitch (floats)

template <int K>
__global__ void __launch_bounds__(256) gemm_kernel(
    const float* __restrict__ X0, int useAcc,
    const float* __restrict__ W, const float* __restrict__ att, int N)
{
    __shared__ __align__(16) float sX[32 * GP];
    __shared__ __align__(16) float sW[32 * GP];
    __shared__ float sAtt[256];

    const float* X = useAcc ? g_acc : X0;

    int t    = threadIdx.x;
    int row0 = blockIdx.x * 128;
    int tx   = t & 15;
    int ty   = t >> 4;
    int lane = t & 31;

    if (t < 256) sAtt[t] = att[t];

    float acc[8][8];
#pragma unroll
    for (int i = 0; i < 8; i++)
#pragma unroll
        for (int j = 0; j < 8; j++) acc[i][j] = 0.f;

    for (int kc = 0; kc < K; kc += 32) {
#pragma unroll
        for (int it = 0; it < 4; it++) {
            int idx = t + it * 256;
            int r = idx >> 3;
            int j = idx & 7;
            int k = 4 * j;

            float4 v = make_float4(0.f, 0.f, 0.f, 0.f);
            int grow = row0 + r;
            if (grow < N)
                v = *reinterpret_cast<const float4*>(X + (size_t)grow * K + kc + k);
            sX[(k + 0) * GP + r] = v.x;
            sX[(k + 1) * GP + r] = v.y;
            sX[(k + 2) * GP + r] = v.z;
            sX[(k + 3) * GP + r] = v.w;

            float4 w = *reinterpret_cast<const float4*>(W + (size_t)r * K + kc + k);
            sW[(k + 0) * GP + r] = w.x;
            sW[(k + 1) * GP + r] = w.y;
            sW[(k + 2) * GP + r] = w.z;
            sW[(k + 3) * GP + r] = w.w;
        }
        __syncthreads();

#pragma unroll 4
        for (int k = 0; k < 32; k++) {
            float4 a0 = *reinterpret_cast<const float4*>(&sX[k * GP + ty * 8]);
            float4 a1 = *reinterpret_cast<const float4*>(&sX[k * GP + ty * 8 + 4]);
            float4 b0 = *reinterpret_cast<const float4*>(&sW[k * GP + tx * 8]);
            float4 b1 = *reinterpret_cast<const float4*>(&sW[k * GP + tx * 8 + 4]);
            float a[8] = {a0.x, a0.y, a0.z, a0.w, a1.x, a1.y, a1.z, a1.w};
            float b[8] = {b0.x, b0.y, b0.z, b0.w, b1.x, b1.y, b1.z, b1.w};
#pragma unroll
            for (int i = 0; i < 8; i++)
#pragma unroll
                for (int j = 0; j < 8; j++)
                    acc[i][j] = fmaf(a[i], b[j], acc[i][j]);
        }
        __syncthreads();
    }

#pragma unroll
    for (int i = 0; i < 8; i++) {
        int grow = row0 + ty * 8 + i;
        if (grow < N) {
            float4 o0 = make_float4(acc[i][0], acc[i][1], acc[i][2], acc[i][3]);
            float4 o1 = make_float4(acc[i][4], acc[i][5], acc[i][6], acc[i][7]);
            float* dst = g_h + (size_t)grow * HC + tx * 8;
            *reinterpret_cast<float4*>(dst)     = o0;
            *reinterpret_cast<float4*>(dst + 4) = o1;
        }
        float dp = 0.f, sp = 0.f;
#pragma unroll
        for (int j = 0; j < 8; j++) {
            int g = tx * 8 + j;
            int base = (g >> 6) * 128 + (g & 63);
            dp = fmaf(acc[i][j], sAtt[base], dp);
            sp = fmaf(acc[i][j], sAtt[base + 64], sp);
        }
#pragma unroll
        for (int o = 4; o > 0; o >>= 1) {
            dp += __shfl_xor_sync(0xffffffffu, dp, o);
            sp += __shfl_xor_sync(0xffffffffu, sp, o);
        }
        if ((lane & 7) == 0 && grow < N) {
            int h = (lane >> 3) & 1;
            g_sdst[grow * 2 + h] = dp;
            g_ssrc[grow * 2 + h] = sp;
        }
    }
}

// ---------------- per-edge raw alpha + leaky relu + global max ----------------
__global__ void __launch_bounds__(256) alpha_kernel(
    const int* __restrict__ ei32, int E, int N, int layer)
{
    int e  = blockIdx.x * blockDim.x + threadIdx.x;
    int ET = E + N;
    float m = -INFINITY;
    if (e < ET) {
        int s, d;
        if (e < E) load_edge(ei32, e, E, s, d);
        else       s = d = e - E;
        float a0 = g_sdst[d * 2]     + g_ssrc[s * 2];
        float a1 = g_sdst[d * 2 + 1] + g_ssrc[s * 2 + 1];
        a0 = (a0 >= 0.f) ? a0 : 0.2f * a0;
        a1 = (a1 >= 0.f) ? a1 : 0.2f * a1;
        g_alpha[e] = make_float2(a0, a1);
        m = fmaxf(a0, a1);
    }
#pragma unroll
    for (int o = 16; o > 0; o >>= 1)
        m = fmaxf(m, __shfl_xor_sync(0xffffffffu, m, o));
    __shared__ float sm[8];
    if ((threadIdx.x & 31) == 0) sm[threadIdx.x >> 5] = m;
    __syncthreads();
    if (threadIdx.x == 0) {
        float bm = sm[0];
#pragma unroll
        for (int i = 1; i < 8; i++) bm = fmaxf(bm, sm[i]);
        atomicMax(&g_maxEnc[layer], encf(bm));
    }
}

// ---------------- exp(alpha - max), per-head sums ----------------
__global__ void __launch_bounds__(256) sumexp_kernel(int E, int N, int layer)
{
    int e  = blockIdx.x * blockDim.x + threadIdx.x;
    int ET = E + N;
    float s0 = 0.f, s1 = 0.f;
    if (e < ET) {
        float mx = decf(g_maxEnc[layer]);
        float2 a = g_alpha[e];
        s0 = __expf(a.x - mx);
        s1 = __expf(a.y - mx);
        g_alpha[e] = make_float2(s0, s1);
    }
#pragma unroll
    for (int o = 16; o > 0; o >>= 1) {
        s0 += __shfl_xor_sync(0xffffffffu, s0, o);
        s1 += __shfl_xor_sync(0xffffffffu, s1, o);
    }
    __shared__ float sm0[8], sm1[8];
    if ((threadIdx.x & 31) == 0) {
        sm0[threadIdx.x >> 5] = s0;
        sm1[threadIdx.x >> 5] = s1;
    }
    __syncthreads();
    if (threadIdx.x == 0) {
        float t0 = 0.f, t1 = 0.f;
#pragma unroll
        for (int i = 0; i < 8; i++) { t0 += sm0[i]; t1 += sm1[i]; }
        atomicAdd(&g_sum[layer * 2],     t0);
        atomicAdd(&g_sum[layer * 2 + 1], t1);
    }
}

__global__ void finalize_sums(int layer)
{
    if (threadIdx.x < 2) {
        int i = layer * 2 + threadIdx.x;
        g_inv[i] = 0.5f / (g_sum[i] + 1e-10f);   // 0.5 = mean over 2 heads
    }
}

// ---------------- gather aggregation: one warp per dst node, no atomics ------
__global__ void __launch_bounds__(256) gather_kernel(
    int N, int layer, float* __restrict__ outp0,
    const float* __restrict__ bias, int doRelu, int toAcc)
{
    int wid  = (blockIdx.x * blockDim.x + threadIdx.x) >> 5;
    int lane = threadIdx.x & 31;
    if (wid >= N) return;
    int d = wid;

    float* outp = toAcc ? g_acc : outp0;

    int beg = g_roff[d];
    int end = g_roff[d + 1];

    float inv0 = g_inv[layer * 2];
    float inv1 = g_inv[layer * 2 + 1];

    const float4* hv = reinterpret_cast<const float4*>(g_h);
    float4 acc = make_float4(0.f, 0.f, 0.f, 0.f);

    for (int base = beg; base < end; base += 32) {
        int idx = base + lane;
        int2  se = make_int2(0, 0);
        float aw0 = 0.f, aw1 = 0.f;
        if (idx < end) {
            se = g_csr[idx];
            float2 al = g_alpha[se.y];
            aw0 = al.x * inv0;
            aw1 = al.y * inv1;
        }
        int cnt = min(32, end - base);
#pragma unroll 4
        for (int j = 0; j < cnt; j++) {
            int   s  = __shfl_sync(0xffffffffu, se.x, j);
            float w0 = __shfl_sync(0xffffffffu, aw0, j);
            float w1 = __shfl_sync(0xffffffffu, aw1, j);
            float ww = (lane < 16) ? w0 : w1;
            float4 v = hv[(size_t)s * 32 + lane];
            acc.x = fmaf(ww, v.x, acc.x);
            acc.y = fmaf(ww, v.y, acc.y);
            acc.z = fmaf(ww, v.z, acc.z);
            acc.w = fmaf(ww, v.w, acc.w);
        }
    }

    acc.x += __shfl_xor_sync(0xffffffffu, acc.x, 16);
    acc.y += __shfl_xor_sync(0xffffffffu, acc.y, 16);
    acc.z += __shfl_xor_sync(0xffffffffu, acc.z, 16);
    acc.w += __shfl_xor_sync(0xffffffffu, acc.w, 16);

    if (lane < 16) {
        const float4 b = reinterpret_cast<const float4*>(bias)[lane];
        acc.x += b.x; acc.y += b.y; acc.z += b.z; acc.w += b.w;
        if (doRelu) {
            acc.x = fmaxf(acc.x, 0.f);
            acc.y = fmaxf(acc.y, 0.f);
            acc.z = fmaxf(acc.z, 0.f);
            acc.w = fmaxf(acc.w, 0.f);
        }
        reinterpret_cast<float4*>(outp + (size_t)d * CD)[lane] = acc;
    }
}

// ---------------- launch ----------------
extern "C" void kernel_launch(void* const* d_in, const int* in_sizes, int n_in,
                              void* d_out, int out_size)
{
    const float* x    = (const float*)d_in[0];
    const int*   ei32 = (const int*)d_in[1];
    const float* W1   = (const float*)d_in[2];
    const float* att1 = (const float*)d_in[3];
    const float* b1   = (const float*)d_in[4];
    const float* W2   = (const float*)d_in[5];
    const float* att2 = (const float*)d_in[6];
    const float* b2   = (const float*)d_in[7];
    float* out = (float*)d_out;

    int N  = in_sizes[0] / FIN;
    int E  = in_sizes[1] / 2;
    int ET = E + N;
    int nb = (N + SCAN_CHUNK - 1) / SCAN_CHUNK;

    detect_kernel<<<1, 64>>>(ei32, E);
    init_kernel<<<(N + 255) / 256, 256>>>(N);
    hist_kernel<<<(E + 255) / 256, 256>>>(ei32, E);
    partial_kernel<<<nb, 256>>>(N);
    scanp_kernel<<<1, 256>>>(nb, N);
    offsets_kernel<<<nb, 256>>>(N);
    scatter_kernel<<<(ET + 255) / 256, 256>>>(ei32, E, N);

    // ---- layer 1 ----
    gemm_kernel<FIN><<<(N + 127) / 128, 256>>>(x, 0, W1, att1, N);
    alpha_kernel<<<(ET + 255) / 256, 256>>>(ei32, E, N, 0);
    sumexp_kernel<<<(ET + 255) / 256, 256>>>(E, N, 0);
    finalize_sums<<<1, 32>>>(0);
    gather_kernel<<<(N * 32 + 255) / 256, 256>>>(N, 0, out, b1, 1, 1);

    // ---- layer 2 ----
    gemm_kernel<CD><<<(N + 127) / 128, 256>>>(x /*unused*/, 1, W2, att2, N);
    alpha_kernel<<<(ET + 255) / 256, 256>>>(ei32, E, N, 1);
    sumexp_kernel<<<(ET + 255) / 256, 256>>>(E, N, 1);
    finalize_sums<<<1, 32>>>(1);
    gather_kernel<<<(N * 32 + 255) / 256, 256>>>(N, 1, out, b2, 0, 0);
}

// round 5
// speedup vs baseline: 2.1025x; 1.2547x over previous
#include <cuda_runtime.h>
#include <math.h>

// Problem constants (shapes fixed by the dataset)
#define HC   128      // HEADS * C
#define CD   64       // C
#define FIN  128      // Fin of layer 1
#define NMAX 50048
#define EMAX 800256
#define ETMAX (NMAX + EMAX)
#define SCAN_CHUNK 2048   // elements per scan block (256 thr x 8)

// ---------------- scratch (device globals; no allocation) ----------------
__device__ __align__(16) float  g_h[(size_t)NMAX * HC];     // GEMM output [N,128]
__device__ __align__(16) float  g_acc[(size_t)NMAX * CD];   // layer-1 out / layer-2 input
__device__ float    g_sdst[NMAX * 2];           // per-node dst-scores [N,H]
__device__ float    g_ssrc[NMAX * 2];           // per-node src-scores [N,H]
__device__ __align__(16) float2 g_alpha[ETMAX]; // per-edge alpha (raw, then exp)
__device__ unsigned g_maxEnc[2];                // order-encoded global max per layer
__device__ float    g_sum[4];                   // per-layer per-head sums
__device__ float    g_inv[4];                   // 0.5 / (sum + eps)
__device__ int      g_is32;                     // 1 if edge_index is int32
// CSR (built once per launch; edges identical for both layers)
__device__ int      g_deg[NMAX];
__device__ int      g_roff[NMAX + 1];
__device__ int      g_cursor[NMAX];
__device__ __align__(8) int2 g_csr[ETMAX];      // (src, edge-id) per incoming edge
__device__ int      g_bsum[256];                // per-block degree sums
__device__ int      g_bbase[256];               // exclusive-scanned block bases

// float <-> order-preserving uint for atomicMax
__device__ __forceinline__ unsigned encf(float f) {
    unsigned u = __float_as_uint(f);
    return (u & 0x80000000u) ? ~u : (u | 0x80000000u);
}
__device__ __forceinline__ float decf(unsigned u) {
    return (u & 0x80000000u) ? __uint_as_float(u & 0x7fffffffu)
                             : __uint_as_float(~u);
}

__device__ __forceinline__ unsigned f2tf32(float f) {
    unsigned r;
    asm("cvt.rna.tf32.f32 %0, %1;" : "=r"(r) : "f"(f));
    return r;
}

__device__ __forceinline__ void mma_tf32(
    float& c0, float& c1, float& c2, float& c3,
    unsigned a0, unsigned a1, unsigned a2, unsigned a3,
    unsigned b0, unsigned b1)
{
    asm volatile(
        "mma.sync.aligned.m16n8k8.row.col.f32.tf32.tf32.f32 "
        "{%0,%1,%2,%3}, {%4,%5,%6,%7}, {%8,%9}, {%0,%1,%2,%3};"
        : "+f"(c0), "+f"(c1), "+f"(c2), "+f"(c3)
        : "r"(a0), "r"(a1), "r"(a2), "r"(a3), "r"(b0), "r"(b1));
}

// unified edge accessor (handles int32 or int64 storage)
__device__ __forceinline__ void load_edge(const int* __restrict__ ei32,
                                          int e, int E, int& s, int& d) {
    if (g_is32) { s = ei32[e];     d = ei32[E + e]; }
    else        { s = ei32[2 * e]; d = ei32[2 * (E + e)]; }
}

// ---------------- dtype detection ----------------
__global__ void detect_kernel(const int* __restrict__ ei32, int E) {
    int t = threadIdx.x;
    unsigned v = 0;
    if (t < 64 && t < E) v = (unsigned)ei32[2 * t + 1];
#pragma unroll
    for (int o = 16; o > 0; o >>= 1) v |= __shfl_xor_sync(0xffffffffu, v, o);
    __shared__ unsigned sh[2];
    if ((t & 31) == 0) sh[t >> 5] = v;
    __syncthreads();
    if (t == 0) g_is32 = ((sh[0] | sh[1]) != 0u) ? 1 : 0;
}

// ---------------- init: deg=1 (self loop), scalars ----------------
__global__ void init_kernel(int N) {
    int i = blockIdx.x * blockDim.x + threadIdx.x;
    if (i < N) g_deg[i] = 1;
    if (i < 2) g_maxEnc[i] = 0u;
    if (i < 4) g_sum[i] = 0.f;
}

// ---------------- CSR build ----------------
__global__ void hist_kernel(const int* __restrict__ ei32, int E) {
    int e = blockIdx.x * blockDim.x + threadIdx.x;
    if (e < E) {
        int s, d;
        load_edge(ei32, e, E, s, d);
        atomicAdd(&g_deg[d], 1);
    }
}

__global__ void __launch_bounds__(256) partial_kernel(int N) {
    __shared__ int sT[256];
    int b = blockIdx.x, t = threadIdx.x;
    int beg = b * SCAN_CHUNK + t * 8;
    int s = 0;
#pragma unroll
    for (int i = 0; i < 8; i++) {
        int idx = beg + i;
        if (idx < N) s += g_deg[idx];
    }
    sT[t] = s;
    __syncthreads();
#pragma unroll
    for (int off = 128; off > 0; off >>= 1) {
        if (t < off) sT[t] += sT[t + off];
        __syncthreads();
    }
    if (t == 0) g_bsum[b] = sT[0];
}

__global__ void scanp_kernel(int nb, int N) {
    __shared__ int sT[256];
    int t = threadIdx.x;
    sT[t] = (t < nb) ? g_bsum[t] : 0;
    __syncthreads();
    for (int off = 1; off < 256; off <<= 1) {
        int v = (t >= off) ? sT[t - off] : 0;
        __syncthreads();
        sT[t] += v;
        __syncthreads();
    }
    if (t < nb) g_bbase[t] = (t == 0) ? 0 : sT[t - 1];
    if (t == 0) g_roff[N] = sT[255];
}

__global__ void __launch_bounds__(256) offsets_kernel(int N) {
    __shared__ int sT[256];
    int b = blockIdx.x, t = threadIdx.x;
    int beg = b * SCAN_CHUNK + t * 8;
    int v[8];
    int s = 0;
#pragma unroll
    for (int i = 0; i < 8; i++) {
        int idx = beg + i;
        v[i] = (idx < N) ? g_deg[idx] : 0;
        s += v[i];
    }
    sT[t] = s;
    __syncthreads();
    for (int off = 1; off < 256; off <<= 1) {
        int x = (t >= off) ? sT[t - off] : 0;
        __syncthreads();
        sT[t] += x;
        __syncthreads();
    }
    int excl = ((t == 0) ? 0 : sT[t - 1]) + g_bbase[b];
#pragma unroll
    for (int i = 0; i < 8; i++) {
        int idx = beg + i;
        if (idx < N) {
            g_roff[idx]   = excl;
            g_cursor[idx] = excl;
            excl += v[i];
        }
    }
}

__global__ void scatter_kernel(const int* __restrict__ ei32, int E, int N) {
    int e = blockIdx.x * blockDim.x + threadIdx.x;
    int ET = E + N;
    if (e >= ET) return;
    int s, d;
    if (e < E) load_edge(ei32, e, E, s, d);
    else       s = d = e - E;
    int pos = atomicAdd(&g_cursor[d], 1);
    g_csr[pos] = make_int2(s, e);
}

// ---------------- tf32 tensor-core GEMM + fused score epilogue --------------
// Hout[N,128] = X[N,K] @ W[128,K]^T ; also g_sdst/g_ssrc per node/head.
// Block: 128 rows x 128 cols, 8 warps (4 m x 2 n), warp tile 32x64,
// mma.m16n8k8.tf32: 2 m-tiles x 8 n-tiles per warp per 8-wide k-step.
#define TP 36   // smem pitch (32 k + 4 pad) -> conflict-free fragment loads

template <int K>
__global__ void __launch_bounds__(256) gemm_tc_kernel(
    const float* __restrict__ X0, int useAcc,
    const float* __restrict__ W, const float* __restrict__ att, int N)
{
    __shared__ __align__(16) unsigned sX[128 * TP];
    __shared__ __align__(16) unsigned sW[128 * TP];
    __shared__ float sAtt[256];

    const float* X = useAcc ? g_acc : X0;

    int t    = threadIdx.x;
    int wid  = t >> 5;
    int lane = t & 31;
    int gid  = lane >> 2;   // group id 0..7
    int tid  = lane & 3;    // thread-in-group 0..3
    int wm   = wid & 3;     // warp m index (0..3) -> 32 rows each
    int wn   = wid >> 2;    // warp n index (0..1) -> 64 cols each == head
    int row0 = blockIdx.x * 128;
    int wrow = wm * 32;     // warp row base within block
    int wcol = wn * 64;     // warp col base (global col = head*64 + ...)

    if (t < 256) sAtt[t] = att[t];

    float c[2][8][4];
#pragma unroll
    for (int mt = 0; mt < 2; mt++)
#pragma unroll
        for (int nt = 0; nt < 8; nt++)
#pragma unroll
            for (int i = 0; i < 4; i++) c[mt][nt][i] = 0.f;

    for (int kc = 0; kc < K; kc += 32) {
        // cooperative load+convert: 128 rows x 32 k each for X and W
#pragma unroll
        for (int it = 0; it < 4; it++) {
            int idx = t + it * 256;
            int r = idx >> 3;        // 0..127
            int q = idx & 7;         // float4 index
            int k = q * 4;

            float4 v = make_float4(0.f, 0.f, 0.f, 0.f);
            int grow = row0 + r;
            if (grow < N)
                v = *reinterpret_cast<const float4*>(X + (size_t)grow * K + kc + k);
            uint4 tv = make_uint4(f2tf32(v.x), f2tf32(v.y), f2tf32(v.z), f2tf32(v.w));
            *reinterpret_cast<uint4*>(&sX[r * TP + k]) = tv;

            float4 w = *reinterpret_cast<const float4*>(W + (size_t)r * K + kc + k);
            uint4 tw = make_uint4(f2tf32(w.x), f2tf32(w.y), f2tf32(w.z), f2tf32(w.w));
            *reinterpret_cast<uint4*>(&sW[r * TP + k]) = tw;
        }
        __syncthreads();

#pragma unroll
        for (int ks = 0; ks < 4; ks++) {
            int k0 = ks * 8;
            unsigned a[2][4];
#pragma unroll
            for (int mt = 0; mt < 2; mt++) {
                int r = wrow + mt * 16 + gid;
                a[mt][0] = sX[r * TP + k0 + tid];
                a[mt][1] = sX[(r + 8) * TP + k0 + tid];
                a[mt][2] = sX[r * TP + k0 + tid + 4];
                a[mt][3] = sX[(r + 8) * TP + k0 + tid + 4];
            }
            unsigned b[8][2];
#pragma unroll
            for (int nt = 0; nt < 8; nt++) {
                int n = wcol + nt * 8 + gid;
                b[nt][0] = sW[n * TP + k0 + tid];
                b[nt][1] = sW[n * TP + k0 + tid + 4];
            }
#pragma unroll
            for (int mt = 0; mt < 2; mt++)
#pragma unroll
                for (int nt = 0; nt < 8; nt++)
                    mma_tf32(c[mt][nt][0], c[mt][nt][1], c[mt][nt][2], c[mt][nt][3],
                             a[mt][0], a[mt][1], a[mt][2], a[mt][3],
                             b[nt][0], b[nt][1]);
        }
        __syncthreads();
    }

    // ---- epilogue: store h + fused per-node scores (head == wn) ----
    float dp[2][2] = {{0.f, 0.f}, {0.f, 0.f}};
    float sp[2][2] = {{0.f, 0.f}, {0.f, 0.f}};

#pragma unroll
    for (int mt = 0; mt < 2; mt++) {
        int rlo = row0 + wrow + mt * 16 + gid;
        int rhi = rlo + 8;
#pragma unroll
        for (int nt = 0; nt < 8; nt++) {
            int cw = nt * 8 + tid * 2;          // col within head (0..63)
            int gc = wcol + cw;                  // col within 128
            float c0 = c[mt][nt][0], c1 = c[mt][nt][1];
            float c2 = c[mt][nt][2], c3 = c[mt][nt][3];
            if (rlo < N)
                *reinterpret_cast<float2*>(g_h + (size_t)rlo * HC + gc) = make_float2(c0, c1);
            if (rhi < N)
                *reinterpret_cast<float2*>(g_h + (size_t)rhi * HC + gc) = make_float2(c2, c3);

            float ad0 = sAtt[wn * 128 + cw],      ad1 = sAtt[wn * 128 + cw + 1];
            float as0 = sAtt[wn * 128 + 64 + cw], as1 = sAtt[wn * 128 + 64 + cw + 1];
            dp[mt][0] = fmaf(c0, ad0, fmaf(c1, ad1, dp[mt][0]));
            sp[mt][0] = fmaf(c0, as0, fmaf(c1, as1, sp[mt][0]));
            dp[mt][1] = fmaf(c2, ad0, fmaf(c3, ad1, dp[mt][1]));
            sp[mt][1] = fmaf(c2, as0, fmaf(c3, as1, sp[mt][1]));
        }
    }
    // reduce over threadID (lanes tid 0..3 within each group)
#pragma unroll
    for (int mt = 0; mt < 2; mt++)
#pragma unroll
        for (int u = 0; u < 2; u++) {
#pragma unroll
            for (int o = 1; o <= 2; o <<= 1) {
                dp[mt][u] += __shfl_xor_sync(0xffffffffu, dp[mt][u], o);
                sp[mt][u] += __shfl_xor_sync(0xffffffffu, sp[mt][u], o);
            }
            if (tid == 0) {
                int row = row0 + wrow + mt * 16 + gid + u * 8;
                if (row < N) {
                    g_sdst[row * 2 + wn] = dp[mt][u];
                    g_ssrc[row * 2 + wn] = sp[mt][u];
                }
            }
        }
}

// ---------------- per-edge raw alpha + leaky relu + global max ----------------
__global__ void __launch_bounds__(256) alpha_kernel(
    const int* __restrict__ ei32, int E, int N, int layer)
{
    int e  = blockIdx.x * blockDim.x + threadIdx.x;
    int ET = E + N;
    float m = -INFINITY;
    if (e < ET) {
        int s, d;
        if (e < E) load_edge(ei32, e, E, s, d);
        else       s = d = e - E;
        float a0 = g_sdst[d * 2]     + g_ssrc[s * 2];
        float a1 = g_sdst[d * 2 + 1] + g_ssrc[s * 2 + 1];
        a0 = (a0 >= 0.f) ? a0 : 0.2f * a0;
        a1 = (a1 >= 0.f) ? a1 : 0.2f * a1;
        g_alpha[e] = make_float2(a0, a1);
        m = fmaxf(a0, a1);
    }
#pragma unroll
    for (int o = 16; o > 0; o >>= 1)
        m = fmaxf(m, __shfl_xor_sync(0xffffffffu, m, o));
    __shared__ float sm[8];
    if ((threadIdx.x & 31) == 0) sm[threadIdx.x >> 5] = m;
    __syncthreads();
    if (threadIdx.x == 0) {
        float bm = sm[0];
#pragma unroll
        for (int i = 1; i < 8; i++) bm = fmaxf(bm, sm[i]);
        atomicMax(&g_maxEnc[layer], encf(bm));
    }
}

// ---------------- exp(alpha - max), per-head sums ----------------
__global__ void __launch_bounds__(256) sumexp_kernel(int E, int N, int layer)
{
    int e  = blockIdx.x * blockDim.x + threadIdx.x;
    int ET = E + N;
    float s0 = 0.f, s1 = 0.f;
    if (e < ET) {
        float mx = decf(g_maxEnc[layer]);
        float2 a = g_alpha[e];
        s0 = __expf(a.x - mx);
        s1 = __expf(a.y - mx);
        g_alpha[e] = make_float2(s0, s1);
    }
#pragma unroll
    for (int o = 16; o > 0; o >>= 1) {
        s0 += __shfl_xor_sync(0xffffffffu, s0, o);
        s1 += __shfl_xor_sync(0xffffffffu, s1, o);
    }
    __shared__ float sm0[8], sm1[8];
    if ((threadIdx.x & 31) == 0) {
        sm0[threadIdx.x >> 5] = s0;
        sm1[threadIdx.x >> 5] = s1;
    }
    __syncthreads();
    if (threadIdx.x == 0) {
        float t0 = 0.f, t1 = 0.f;
#pragma unroll
        for (int i = 0; i < 8; i++) { t0 += sm0[i]; t1 += sm1[i]; }
        atomicAdd(&g_sum[layer * 2],     t0);
        atomicAdd(&g_sum[layer * 2 + 1], t1);
    }
}

__global__ void finalize_sums(int layer)
{
    if (threadIdx.x < 2) {
        int i = layer * 2 + threadIdx.x;
        g_inv[i] = 0.5f / (g_sum[i] + 1e-10f);   // 0.5 = mean over 2 heads
    }
}

// ---------------- gather aggregation: one warp per dst node, no atomics ------
__global__ void __launch_bounds__(256) gather_kernel(
    int N, int layer, float* __restrict__ outp0,
    const float* __restrict__ bias, int doRelu, int toAcc)
{
    int wid  = (blockIdx.x * blockDim.x + threadIdx.x) >> 5;
    int lane = threadIdx.x & 31;
    if (wid >= N) return;
    int d = wid;

    float* outp = toAcc ? g_acc : outp0;

    int beg = g_roff[d];
    int end = g_roff[d + 1];

    float inv0 = g_inv[layer * 2];
    float inv1 = g_inv[layer * 2 + 1];

    const float4* hv = reinterpret_cast<const float4*>(g_h);
    float4 acc = make_float4(0.f, 0.f, 0.f, 0.f);

    for (int base = beg; base < end; base += 32) {
        int idx = base + lane;
        int2  se = make_int2(0, 0);
        float aw0 = 0.f, aw1 = 0.f;
        if (idx < end) {
            se = g_csr[idx];
            float2 al = g_alpha[se.y];
            aw0 = al.x * inv0;
            aw1 = al.y * inv1;
        }
        int cnt = min(32, end - base);
#pragma unroll 4
        for (int j = 0; j < cnt; j++) {
            int   s  = __shfl_sync(0xffffffffu, se.x, j);
            float w0 = __shfl_sync(0xffffffffu, aw0, j);
            float w1 = __shfl_sync(0xffffffffu, aw1, j);
            float ww = (lane < 16) ? w0 : w1;
            float4 v = hv[(size_t)s * 32 + lane];
            acc.x = fmaf(ww, v.x, acc.x);
            acc.y = fmaf(ww, v.y, acc.y);
            acc.z = fmaf(ww, v.z, acc.z);
            acc.w = fmaf(ww, v.w, acc.w);
        }
    }

    acc.x += __shfl_xor_sync(0xffffffffu, acc.x, 16);
    acc.y += __shfl_xor_sync(0xffffffffu, acc.y, 16);
    acc.z += __shfl_xor_sync(0xffffffffu, acc.z, 16);
    acc.w += __shfl_xor_sync(0xffffffffu, acc.w, 16);

    if (lane < 16) {
        const float4 b = reinterpret_cast<const float4*>(bias)[lane];
        acc.x += b.x; acc.y += b.y; acc.z += b.z; acc.w += b.w;
        if (doRelu) {
            acc.x = fmaxf(acc.x, 0.f);
            acc.y = fmaxf(acc.y, 0.f);
            acc.z = fmaxf(acc.z, 0.f);
            acc.w = fmaxf(acc.w, 0.f);
        }
        reinterpret_cast<float4*>(outp + (size_t)d * CD)[lane] = acc;
    }
}

// ---------------- launch ----------------
extern "C" void kernel_launch(void* const* d_in, const int* in_sizes, int n_in,
                              void* d_out, int out_size)
{
    const float* x    = (const float*)d_in[0];
    const int*   ei32 = (const int*)d_in[1];
    const float* W1   = (const float*)d_in[2];
    const float* att1 = (const float*)d_in[3];
    const float* b1   = (const float*)d_in[4];
    const float* W2   = (const float*)d_in[5];
    const float* att2 = (const float*)d_in[6];
    const float* b2   = (const float*)d_in[7];
    float* out = (float*)d_out;

    int N  = in_sizes[0] / FIN;
    int E  = in_sizes[1] / 2;
    int ET = E + N;
    int nb = (N + SCAN_CHUNK - 1) / SCAN_CHUNK;

    detect_kernel<<<1, 64>>>(ei32, E);
    init_kernel<<<(N + 255) / 256, 256>>>(N);
    hist_kernel<<<(E + 255) / 256, 256>>>(ei32, E);
    partial_kernel<<<nb, 256>>>(N);
    scanp_kernel<<<1, 256>>>(nb, N);
    offsets_kernel<<<nb, 256>>>(N);
    scatter_kernel<<<(ET + 255) / 256, 256>>>(ei32, E, N);

    // ---- layer 1 ----
    gemm_tc_kernel<FIN><<<(N + 127) / 128, 256>>>(x, 0, W1, att1, N);
    alpha_kernel<<<(ET + 255) / 256, 256>>>(ei32, E, N, 0);
    sumexp_kernel<<<(ET + 255) / 256, 256>>>(E, N, 0);
    finalize_sums<<<1, 32>>>(0);
    gather_kernel<<<(N * 32 + 255) / 256, 256>>>(N, 0, out, b1, 1, 1);

    // ---- layer 2 ----
    gemm_tc_kernel<CD><<<(N + 127) / 128, 256>>>(x /*unused*/, 1, W2, att2, N);
    alpha_kernel<<<(ET + 255) / 256, 256>>>(ei32, E, N, 1);
    sumexp_kernel<<<(ET + 255) / 256, 256>>>(E, N, 1);
    finalize_sums<<<1, 32>>>(1);
    gather_kernel<<<(N * 32 + 255) / 256, 256>>>(N, 1, out, b2, 0, 0);
}

// round 6
// speedup vs baseline: 2.3173x; 1.1022x over previous
#include <cuda_runtime.h>
#include <math.h>

// Problem constants (shapes fixed by the dataset)
#define HC   128      // HEADS * C
#define CD   64       // C
#define FIN  128      // Fin of layer 1
#define NMAX 50048
#define EMAX 800256
#define ETMAX (NMAX + EMAX)
#define SCAN_CHUNK 2048   // elements per scan block (256 thr x 8)

// ---------------- scratch (device globals; no allocation) ----------------
__device__ __align__(16) float  g_h[(size_t)NMAX * HC];     // GEMM output [N,128]
__device__ __align__(16) float  g_acc[(size_t)NMAX * CD];   // layer-1 out / layer-2 input
__device__ float    g_sdst[NMAX * 2];           // per-node dst-scores [N,H]
__device__ float    g_ssrc[NMAX * 2];           // per-node src-scores [N,H]
__device__ __align__(16) float2 g_alpha[ETMAX]; // per-edge exp(alpha)
__device__ float    g_sum[4];                   // per-layer per-head exp sums
__device__ int      g_is32;                     // 1 if edge_index is int32
// CSR (built once per launch; edges identical for both layers)
__device__ int      g_deg[NMAX];
__device__ int      g_roff[NMAX + 1];
__device__ int      g_cursor[NMAX];
__device__ __align__(8) int2 g_csr[ETMAX];      // (src, edge-id) per incoming edge
__device__ int      g_bsum[256];                // per-block degree sums
__device__ int      g_bbase[256];               // exclusive-scanned block bases

__device__ __forceinline__ unsigned f2tf32(float f) {
    unsigned r;
    asm("cvt.rna.tf32.f32 %0, %1;" : "=r"(r) : "f"(f));
    return r;
}

__device__ __forceinline__ void mma_tf32(
    float& c0, float& c1, float& c2, float& c3,
    unsigned a0, unsigned a1, unsigned a2, unsigned a3,
    unsigned b0, unsigned b1)
{
    asm volatile(
        "mma.sync.aligned.m16n8k8.row.col.f32.tf32.tf32.f32 "
        "{%0,%1,%2,%3}, {%4,%5,%6,%7}, {%8,%9}, {%0,%1,%2,%3};"
        : "+f"(c0), "+f"(c1), "+f"(c2), "+f"(c3)
        : "r"(a0), "r"(a1), "r"(a2), "r"(a3), "r"(b0), "r"(b1));
}

// unified edge accessor (handles int32 or int64 storage)
__device__ __forceinline__ void load_edge(const int* __restrict__ ei32,
                                          int e, int E, int& s, int& d) {
    if (g_is32) { s = ei32[e];     d = ei32[E + e]; }
    else        { s = ei32[2 * e]; d = ei32[2 * (E + e)]; }
}

// ---------------- init (deg=1, sums=0) + dtype detection (block 0) ----------
// int64 edge values < 2^31 have all-zero odd 32-bit words; int32 payload doesn't.
__global__ void init_detect_kernel(const int* __restrict__ ei32, int E, int N) {
    int i = blockIdx.x * blockDim.x + threadIdx.x;
    if (i < N) g_deg[i] = 1;
    if (i < 4) g_sum[i] = 0.f;
    if (blockIdx.x == 0 && threadIdx.x < 64) {
        int t = threadIdx.x;
        unsigned v = (t < E) ? (unsigned)ei32[2 * t + 1] : 0u;
#pragma unroll
        for (int o = 16; o > 0; o >>= 1) v |= __shfl_xor_sync(0xffffffffu, v, o);
        __shared__ unsigned sh[2];
        if ((t & 31) == 0) sh[t >> 5] = v;
        __syncthreads();
        if (t == 0) g_is32 = ((sh[0] | sh[1]) != 0u) ? 1 : 0;
    }
}

// ---------------- CSR build ----------------
__global__ void hist_kernel(const int* __restrict__ ei32, int E) {
    int e = blockIdx.x * blockDim.x + threadIdx.x;
    if (e < E) {
        int s, d;
        load_edge(ei32, e, E, s, d);
        atomicAdd(&g_deg[d], 1);
    }
}

__global__ void __launch_bounds__(256) partial_kernel(int N) {
    __shared__ int sT[256];
    int b = blockIdx.x, t = threadIdx.x;
    int beg = b * SCAN_CHUNK + t * 8;
    int s = 0;
#pragma unroll
    for (int i = 0; i < 8; i++) {
        int idx = beg + i;
        if (idx < N) s += g_deg[idx];
    }
    sT[t] = s;
    __syncthreads();
#pragma unroll
    for (int off = 128; off > 0; off >>= 1) {
        if (t < off) sT[t] += sT[t + off];
        __syncthreads();
    }
    if (t == 0) g_bsum[b] = sT[0];
}

__global__ void scanp_kernel(int nb, int N) {
    __shared__ int sT[256];
    int t = threadIdx.x;
    sT[t] = (t < nb) ? g_bsum[t] : 0;
    __syncthreads();
    for (int off = 1; off < 256; off <<= 1) {
        int v = (t >= off) ? sT[t - off] : 0;
        __syncthreads();
        sT[t] += v;
        __syncthreads();
    }
    if (t < nb) g_bbase[t] = (t == 0) ? 0 : sT[t - 1];
    if (t == 0) g_roff[N] = sT[255];
}

__global__ void __launch_bounds__(256) offsets_kernel(int N) {
    __shared__ int sT[256];
    int b = blockIdx.x, t = threadIdx.x;
    int beg = b * SCAN_CHUNK + t * 8;
    int v[8];
    int s = 0;
#pragma unroll
    for (int i = 0; i < 8; i++) {
        int idx = beg + i;
        v[i] = (idx < N) ? g_deg[idx] : 0;
        s += v[i];
    }
    sT[t] = s;
    __syncthreads();
    for (int off = 1; off < 256; off <<= 1) {
        int x = (t >= off) ? sT[t - off] : 0;
        __syncthreads();
        sT[t] += x;
        __syncthreads();
    }
    int excl = ((t == 0) ? 0 : sT[t - 1]) + g_bbase[b];
#pragma unroll
    for (int i = 0; i < 8; i++) {
        int idx = beg + i;
        if (idx < N) {
            g_roff[idx]   = excl;
            g_cursor[idx] = excl;
            excl += v[i];
        }
    }
}

__global__ void scatter_kernel(const int* __restrict__ ei32, int E, int N) {
    int e = blockIdx.x * blockDim.x + threadIdx.x;
    int ET = E + N;
    if (e >= ET) return;
    int s, d;
    if (e < E) load_edge(ei32, e, E, s, d);
    else       s = d = e - E;
    int pos = atomicAdd(&g_cursor[d], 1);
    g_csr[pos] = make_int2(s, e);
}

// ---------------- tf32 tensor-core GEMM + fused score epilogue --------------
#define TP 36   // smem pitch (32 k + 4 pad) -> conflict-free fragment loads

template <int K>
__global__ void __launch_bounds__(256) gemm_tc_kernel(
    const float* __restrict__ X0, int useAcc,
    const float* __restrict__ W, const float* __restrict__ att, int N)
{
    __shared__ __align__(16) unsigned sX[128 * TP];
    __shared__ __align__(16) unsigned sW[128 * TP];
    __shared__ float sAtt[256];

    const float* X = useAcc ? g_acc : X0;

    int t    = threadIdx.x;
    int wid  = t >> 5;
    int lane = t & 31;
    int gid  = lane >> 2;   // group id 0..7
    int tid  = lane & 3;    // thread-in-group 0..3
    int wm   = wid & 3;     // warp m index
    int wn   = wid >> 2;    // warp n index == head
    int row0 = blockIdx.x * 128;
    int wrow = wm * 32;
    int wcol = wn * 64;

    if (t < 256) sAtt[t] = att[t];

    float c[2][8][4];
#pragma unroll
    for (int mt = 0; mt < 2; mt++)
#pragma unroll
        for (int nt = 0; nt < 8; nt++)
#pragma unroll
            for (int i = 0; i < 4; i++) c[mt][nt][i] = 0.f;

    for (int kc = 0; kc < K; kc += 32) {
#pragma unroll
        for (int it = 0; it < 4; it++) {
            int idx = t + it * 256;
            int r = idx >> 3;
            int q = idx & 7;
            int k = q * 4;

            float4 v = make_float4(0.f, 0.f, 0.f, 0.f);
            int grow = row0 + r;
            if (grow < N)
                v = *reinterpret_cast<const float4*>(X + (size_t)grow * K + kc + k);
            uint4 tv = make_uint4(f2tf32(v.x), f2tf32(v.y), f2tf32(v.z), f2tf32(v.w));
            *reinterpret_cast<uint4*>(&sX[r * TP + k]) = tv;

            float4 w = *reinterpret_cast<const float4*>(W + (size_t)r * K + kc + k);
            uint4 tw = make_uint4(f2tf32(w.x), f2tf32(w.y), f2tf32(w.z), f2tf32(w.w));
            *reinterpret_cast<uint4*>(&sW[r * TP + k]) = tw;
        }
        __syncthreads();

#pragma unroll
        for (int ks = 0; ks < 4; ks++) {
            int k0 = ks * 8;
            unsigned a[2][4];
#pragma unroll
            for (int mt = 0; mt < 2; mt++) {
                int r = wrow + mt * 16 + gid;
                a[mt][0] = sX[r * TP + k0 + tid];
                a[mt][1] = sX[(r + 8) * TP + k0 + tid];
                a[mt][2] = sX[r * TP + k0 + tid + 4];
                a[mt][3] = sX[(r + 8) * TP + k0 + tid + 4];
            }
            unsigned b[8][2];
#pragma unroll
            for (int nt = 0; nt < 8; nt++) {
                int n = wcol + nt * 8 + gid;
                b[nt][0] = sW[n * TP + k0 + tid];
                b[nt][1] = sW[n * TP + k0 + tid + 4];
            }
#pragma unroll
            for (int mt = 0; mt < 2; mt++)
#pragma unroll
                for (int nt = 0; nt < 8; nt++)
                    mma_tf32(c[mt][nt][0], c[mt][nt][1], c[mt][nt][2], c[mt][nt][3],
                             a[mt][0], a[mt][1], a[mt][2], a[mt][3],
                             b[nt][0], b[nt][1]);
        }
        __syncthreads();
    }

    float dp[2][2] = {{0.f, 0.f}, {0.f, 0.f}};
    float sp[2][2] = {{0.f, 0.f}, {0.f, 0.f}};

#pragma unroll
    for (int mt = 0; mt < 2; mt++) {
        int rlo = row0 + wrow + mt * 16 + gid;
        int rhi = rlo + 8;
#pragma unroll
        for (int nt = 0; nt < 8; nt++) {
            int cw = nt * 8 + tid * 2;
            int gc = wcol + cw;
            float c0 = c[mt][nt][0], c1 = c[mt][nt][1];
            float c2 = c[mt][nt][2], c3 = c[mt][nt][3];
            if (rlo < N)
                *reinterpret_cast<float2*>(g_h + (size_t)rlo * HC + gc) = make_float2(c0, c1);
            if (rhi < N)
                *reinterpret_cast<float2*>(g_h + (size_t)rhi * HC + gc) = make_float2(c2, c3);

            float ad0 = sAtt[wn * 128 + cw],      ad1 = sAtt[wn * 128 + cw + 1];
            float as0 = sAtt[wn * 128 + 64 + cw], as1 = sAtt[wn * 128 + 64 + cw + 1];
            dp[mt][0] = fmaf(c0, ad0, fmaf(c1, ad1, dp[mt][0]));
            sp[mt][0] = fmaf(c0, as0, fmaf(c1, as1, sp[mt][0]));
            dp[mt][1] = fmaf(c2, ad0, fmaf(c3, ad1, dp[mt][1]));
            sp[mt][1] = fmaf(c2, as0, fmaf(c3, as1, sp[mt][1]));
        }
    }
#pragma unroll
    for (int mt = 0; mt < 2; mt++)
#pragma unroll
        for (int u = 0; u < 2; u++) {
#pragma unroll
            for (int o = 1; o <= 2; o <<= 1) {
                dp[mt][u] += __shfl_xor_sync(0xffffffffu, dp[mt][u], o);
                sp[mt][u] += __shfl_xor_sync(0xffffffffu, sp[mt][u], o);
            }
            if (tid == 0) {
                int row = row0 + wrow + mt * 16 + gid + u * 8;
                if (row < N) {
                    g_sdst[row * 2 + wn] = dp[mt][u];
                    g_ssrc[row * 2 + wn] = sp[mt][u];
                }
            }
        }
}

// ---------------- fused: alpha + leaky relu + exp + per-head sums -----------
// Global softmax is shift-invariant: exp(a)/sum(exp(a)) == exp(a-m)/sum(exp(a-m)).
// Scores are O(1) by construction, so unshifted exp is safe in fp32.
__global__ void __launch_bounds__(256) alpha_sum_kernel(
    const int* __restrict__ ei32, int E, int N, int layer)
{
    int e  = blockIdx.x * blockDim.x + threadIdx.x;
    int ET = E + N;
    float s0 = 0.f, s1 = 0.f;
    if (e < ET) {
        int s, d;
        if (e < E) load_edge(ei32, e, E, s, d);
        else       s = d = e - E;
        float a0 = g_sdst[d * 2]     + g_ssrc[s * 2];
        float a1 = g_sdst[d * 2 + 1] + g_ssrc[s * 2 + 1];
        a0 = (a0 >= 0.f) ? a0 : 0.2f * a0;
        a1 = (a1 >= 0.f) ? a1 : 0.2f * a1;
        s0 = __expf(a0);
        s1 = __expf(a1);
        g_alpha[e] = make_float2(s0, s1);
    }
#pragma unroll
    for (int o = 16; o > 0; o >>= 1) {
        s0 += __shfl_xor_sync(0xffffffffu, s0, o);
        s1 += __shfl_xor_sync(0xffffffffu, s1, o);
    }
    __shared__ float sm0[8], sm1[8];
    if ((threadIdx.x & 31) == 0) {
        sm0[threadIdx.x >> 5] = s0;
        sm1[threadIdx.x >> 5] = s1;
    }
    __syncthreads();
    if (threadIdx.x == 0) {
        float t0 = 0.f, t1 = 0.f;
#pragma unroll
        for (int i = 0; i < 8; i++) { t0 += sm0[i]; t1 += sm1[i]; }
        atomicAdd(&g_sum[layer * 2],     t0);
        atomicAdd(&g_sum[layer * 2 + 1], t1);
    }
}

// ---------------- gather aggregation: one warp per dst node, no atomics ------
__global__ void __launch_bounds__(256) gather_kernel(
    int N, int layer, float* __restrict__ outp0,
    const float* __restrict__ bias, int doRelu, int toAcc)
{
    int wid  = (blockIdx.x * blockDim.x + threadIdx.x) >> 5;
    int lane = threadIdx.x & 31;
    if (wid >= N) return;
    int d = wid;

    float* outp = toAcc ? g_acc : outp0;

    int beg = g_roff[d];
    int end = g_roff[d + 1];

    float inv0 = 0.5f / (g_sum[layer * 2]     + 1e-10f);
    float inv1 = 0.5f / (g_sum[layer * 2 + 1] + 1e-10f);

    const float4* hv = reinterpret_cast<const float4*>(g_h);
    float4 acc = make_float4(0.f, 0.f, 0.f, 0.f);

    for (int base = beg; base < end; base += 32) {
        int idx = base + lane;
        int2  se = make_int2(0, 0);
        float aw0 = 0.f, aw1 = 0.f;
        if (idx < end) {
            se = g_csr[idx];
            float2 al = g_alpha[se.y];
            aw0 = al.x * inv0;
            aw1 = al.y * inv1;
        }
        int cnt = min(32, end - base);
#pragma unroll 4
        for (int j = 0; j < cnt; j++) {
            int   s  = __shfl_sync(0xffffffffu, se.x, j);
            float w0 = __shfl_sync(0xffffffffu, aw0, j);
            float w1 = __shfl_sync(0xffffffffu, aw1, j);
            float ww = (lane < 16) ? w0 : w1;
            float4 v = hv[(size_t)s * 32 + lane];
            acc.x = fmaf(ww, v.x, acc.x);
            acc.y = fmaf(ww, v.y, acc.y);
            acc.z = fmaf(ww, v.z, acc.z);
            acc.w = fmaf(ww, v.w, acc.w);
        }
    }

    acc.x += __shfl_xor_sync(0xffffffffu, acc.x, 16);
    acc.y += __shfl_xor_sync(0xffffffffu, acc.y, 16);
    acc.z += __shfl_xor_sync(0xffffffffu, acc.z, 16);
    acc.w += __shfl_xor_sync(0xffffffffu, acc.w, 16);

    if (lane < 16) {
        const float4 b = reinterpret_cast<const float4*>(bias)[lane];
        acc.x += b.x; acc.y += b.y; acc.z += b.z; acc.w += b.w;
        if (doRelu) {
            acc.x = fmaxf(acc.x, 0.f);
            acc.y = fmaxf(acc.y, 0.f);
            acc.z = fmaxf(acc.z, 0.f);
            acc.w = fmaxf(acc.w, 0.f);
        }
        reinterpret_cast<float4*>(outp + (size_t)d * CD)[lane] = acc;
    }
}

// ---------------- launch ----------------
extern "C" void kernel_launch(void* const* d_in, const int* in_sizes, int n_in,
                              void* d_out, int out_size)
{
    const float* x    = (const float*)d_in[0];
    const int*   ei32 = (const int*)d_in[1];
    const float* W1   = (const float*)d_in[2];
    const float* att1 = (const float*)d_in[3];
    const float* b1   = (const float*)d_in[4];
    const float* W2   = (const float*)d_in[5];
    const float* att2 = (const float*)d_in[6];
    const float* b2   = (const float*)d_in[7];
    float* out = (float*)d_out;

    int N  = in_sizes[0] / FIN;
    int E  = in_sizes[1] / 2;
    int ET = E + N;
    int nb = (N + SCAN_CHUNK - 1) / SCAN_CHUNK;

    init_detect_kernel<<<(N + 255) / 256, 256>>>(ei32, E, N);
    // GEMM1 is independent of CSR build; do it early
    gemm_tc_kernel<FIN><<<(N + 127) / 128, 256>>>(x, 0, W1, att1, N);
    hist_kernel<<<(E + 255) / 256, 256>>>(ei32, E);
    partial_kernel<<<nb, 256>>>(N);
    scanp_kernel<<<1, 256>>>(nb, N);
    offsets_kernel<<<nb, 256>>>(N);
    scatter_kernel<<<(ET + 255) / 256, 256>>>(ei32, E, N);

    // ---- layer 1 ----
    alpha_sum_kernel<<<(ET + 255) / 256, 256>>>(ei32, E, N, 0);
    gather_kernel<<<(N * 32 + 255) / 256, 256>>>(N, 0, out, b1, 1, 1);

    // ---- layer 2 ----
    gemm_tc_kernel<CD><<<(N + 127) / 128, 256>>>(x /*unused*/, 1, W2, att2, N);
    alpha_sum_kernel<<<(ET + 255) / 256, 256>>>(ei32, E, N, 1);
    gather_kernel<<<(N * 32 + 255) / 256, 256>>>(N, 1, out, b2, 0, 0);
}

// round 8
// speedup vs baseline: 2.4125x; 1.0411x over previous
#include <cuda_runtime.h>
#include <cuda_fp16.h>
#include <math.h>

// Problem constants (shapes fixed by the dataset)
#define HC   128      // HEADS * C
#define CD   64       // C
#define FIN  128      // Fin of layer 1
#define NMAX 50048
#define EMAX 800256
#define ETMAX (NMAX + EMAX)
#define SCAN_CHUNK 2048   // elements per scan block (256 thr x 8)
#define HSCALE 4096.0f    // fp16 storage scale (keeps layer-2 h out of subnormals)
#define HSCALE_INV (1.0f / 4096.0f)

// ---------------- scratch (device globals; no allocation) ----------------
__device__ __align__(16) __half g_hh[(size_t)NMAX * HC];    // GEMM output * HSCALE, fp16
__device__ __align__(16) float  g_acc[(size_t)NMAX * CD];   // layer-1 out / layer-2 input (fp32)
__device__ __align__(8)  float  g_sdst[NMAX * 2];           // per-node dst-scores [N,H]
__device__ __align__(8)  float  g_ssrc[NMAX * 2];           // per-node src-scores [N,H]
__device__ float    g_sum[4];                   // per-layer per-head exp sums
__device__ int      g_is32;                     // 1 if edge_index is int32
// CSR (built once per launch; edges identical for both layers)
__device__ int      g_deg[NMAX];
__device__ int      g_roff[NMAX + 1];
__device__ int      g_cursor[NMAX];
__device__ int      g_csr[ETMAX];               // src per incoming edge (dst-sorted)
__device__ int      g_bsum[256];                // per-block degree sums
__device__ int      g_bbase[256];               // exclusive-scanned block bases

__device__ __forceinline__ unsigned f2tf32(float f) {
    unsigned r;
    asm("cvt.rna.tf32.f32 %0, %1;" : "=r"(r) : "f"(f));
    return r;
}

__device__ __forceinline__ void mma_tf32(
    float& c0, float& c1, float& c2, float& c3,
    unsigned a0, unsigned a1, unsigned a2, unsigned a3,
    unsigned b0, unsigned b1)
{
    asm volatile(
        "mma.sync.aligned.m16n8k8.row.col.f32.tf32.tf32.f32 "
        "{%0,%1,%2,%3}, {%4,%5,%6,%7}, {%8,%9}, {%0,%1,%2,%3};"
        : "+f"(c0), "+f"(c1), "+f"(c2), "+f"(c3)
        : "r"(a0), "r"(a1), "r"(a2), "r"(a3), "r"(b0), "r"(b1));
}

// unified edge accessor (handles int32 or int64 storage)
__device__ __forceinline__ void load_edge(const int* __restrict__ ei32,
                                          int e, int E, int& s, int& d) {
    if (g_is32) { s = ei32[e];     d = ei32[E + e]; }
    else        { s = ei32[2 * e]; d = ei32[2 * (E + e)]; }
}

// leaky-relu(0.2) then exp
__device__ __forceinline__ float lrexp(float a) {
    a = (a >= 0.f) ? a : 0.2f * a;
    return __expf(a);
}

// ---------------- init (deg=1, sums=0) + dtype detection (block 0) ----------
__global__ void init_detect_kernel(const int* __restrict__ ei32, int E, int N) {
    int i = blockIdx.x * blockDim.x + threadIdx.x;
    if (i < N) g_deg[i] = 1;
    if (i < 4) g_sum[i] = 0.f;
    if (blockIdx.x == 0 && threadIdx.x < 64) {
        int t = threadIdx.x;
        unsigned v = (t < E) ? (unsigned)ei32[2 * t + 1] : 0u;
#pragma unroll
        for (int o = 16; o > 0; o >>= 1) v |= __shfl_xor_sync(0xffffffffu, v, o);
        __shared__ unsigned sh[2];
        if ((t & 31) == 0) sh[t >> 5] = v;
        __syncthreads();
        if (t == 0) g_is32 = ((sh[0] | sh[1]) != 0u) ? 1 : 0;
    }
}

// ---------------- CSR build ----------------
__global__ void hist_kernel(const int* __restrict__ ei32, int E) {
    int e = blockIdx.x * blockDim.x + threadIdx.x;
    if (e < E) {
        int s, d;
        load_edge(ei32, e, E, s, d);
        atomicAdd(&g_deg[d], 1);
    }
}

__global__ void __launch_bounds__(256) partial_kernel(int N) {
    __shared__ int sT[256];
    int b = blockIdx.x, t = threadIdx.x;
    int beg = b * SCAN_CHUNK + t * 8;
    int s = 0;
#pragma unroll
    for (int i = 0; i < 8; i++) {
        int idx = beg + i;
        if (idx < N) s += g_deg[idx];
    }
    sT[t] = s;
    __syncthreads();
#pragma unroll
    for (int off = 128; off > 0; off >>= 1) {
        if (t < off) sT[t] += sT[t + off];
        __syncthreads();
    }
    if (t == 0) g_bsum[b] = sT[0];
}

__global__ void scanp_kernel(int nb, int N) {
    __shared__ int sT[256];
    int t = threadIdx.x;
    sT[t] = (t < nb) ? g_bsum[t] : 0;
    __syncthreads();
    for (int off = 1; off < 256; off <<= 1) {
        int v = (t >= off) ? sT[t - off] : 0;
        __syncthreads();
        sT[t] += v;
        __syncthreads();
    }
    if (t < nb) g_bbase[t] = (t == 0) ? 0 : sT[t - 1];
    if (t == 0) g_roff[N] = sT[255];
}

__global__ void __launch_bounds__(256) offsets_kernel(int N) {
    __shared__ int sT[256];
    int b = blockIdx.x, t = threadIdx.x;
    int beg = b * SCAN_CHUNK + t * 8;
    int v[8];
    int s = 0;
#pragma unroll
    for (int i = 0; i < 8; i++) {
        int idx = beg + i;
        v[i] = (idx < N) ? g_deg[idx] : 0;
        s += v[i];
    }
    sT[t] = s;
    __syncthreads();
    for (int off = 1; off < 256; off <<= 1) {
        int x = (t >= off) ? sT[t - off] : 0;
        __syncthreads();
        sT[t] += x;
        __syncthreads();
    }
    int excl = ((t == 0) ? 0 : sT[t - 1]) + g_bbase[b];
#pragma unroll
    for (int i = 0; i < 8; i++) {
        int idx = beg + i;
        if (idx < N) {
            g_roff[idx]   = excl;
            g_cursor[idx] = excl;
            excl += v[i];
        }
    }
}

// scatter to CSR + fused layer-0 softmax-denominator sums (scores ready: gemm1 ran)
__global__ void __launch_bounds__(256) scatter_sum_kernel(
    const int* __restrict__ ei32, int E, int N)
{
    int e = blockIdx.x * blockDim.x + threadIdx.x;
    int ET = E + N;
    float s0 = 0.f, s1 = 0.f;
    if (e < ET) {
        int s, d;
        if (e < E) load_edge(ei32, e, E, s, d);
        else       s = d = e - E;
        int pos = atomicAdd(&g_cursor[d], 1);
        g_csr[pos] = s;
        s0 = lrexp(g_sdst[d * 2]     + g_ssrc[s * 2]);
        s1 = lrexp(g_sdst[d * 2 + 1] + g_ssrc[s * 2 + 1]);
    }
#pragma unroll
    for (int o = 16; o > 0; o >>= 1) {
        s0 += __shfl_xor_sync(0xffffffffu, s0, o);
        s1 += __shfl_xor_sync(0xffffffffu, s1, o);
    }
    __shared__ float sm0[8], sm1[8];
    if ((threadIdx.x & 31) == 0) {
        sm0[threadIdx.x >> 5] = s0;
        sm1[threadIdx.x >> 5] = s1;
    }
    __syncthreads();
    if (threadIdx.x == 0) {
        float t0 = 0.f, t1 = 0.f;
#pragma unroll
        for (int i = 0; i < 8; i++) { t0 += sm0[i]; t1 += sm1[i]; }
        atomicAdd(&g_sum[0], t0);
        atomicAdd(&g_sum[1], t1);
    }
}

// layer-2 softmax-denominator sums only (no array writes)
__global__ void __launch_bounds__(256) sum2_kernel(
    const int* __restrict__ ei32, int E, int N)
{
    int e = blockIdx.x * blockDim.x + threadIdx.x;
    int ET = E + N;
    float s0 = 0.f, s1 = 0.f;
    if (e < ET) {
        int s, d;
        if (e < E) load_edge(ei32, e, E, s, d);
        else       s = d = e - E;
        s0 = lrexp(g_sdst[d * 2]     + g_ssrc[s * 2]);
        s1 = lrexp(g_sdst[d * 2 + 1] + g_ssrc[s * 2 + 1]);
    }
#pragma unroll
    for (int o = 16; o > 0; o >>= 1) {
        s0 += __shfl_xor_sync(0xffffffffu, s0, o);
        s1 += __shfl_xor_sync(0xffffffffu, s1, o);
    }
    __shared__ float sm0[8], sm1[8];
    if ((threadIdx.x & 31) == 0) {
        sm0[threadIdx.x >> 5] = s0;
        sm1[threadIdx.x >> 5] = s1;
    }
    __syncthreads();
    if (threadIdx.x == 0) {
        float t0 = 0.f, t1 = 0.f;
#pragma unroll
        for (int i = 0; i < 8; i++) { t0 += sm0[i]; t1 += sm1[i]; }
        atomicAdd(&g_sum[2], t0);
        atomicAdd(&g_sum[3], t1);
    }
}

// ---------------- tf32 tensor-core GEMM + fused score epilogue --------------
// Writes h*HSCALE as fp16 (gather unscales); scores from fp32 accumulators.
#define TP 36   // smem pitch (32 k + 4 pad) -> conflict-free fragment loads

template <int K>
__global__ void __launch_bounds__(256) gemm_tc_kernel(
    const float* __restrict__ X0, int useAcc,
    const float* __restrict__ W, const float* __restrict__ att, int N)
{
    __shared__ __align__(16) unsigned sX[128 * TP];
    __shared__ __align__(16) unsigned sW[128 * TP];
    __shared__ float sAtt[256];

    const float* X = useAcc ? g_acc : X0;

    int t    = threadIdx.x;
    int wid  = t >> 5;
    int lane = t & 31;
    int gid  = lane >> 2;   // group id 0..7
    int tid  = lane & 3;    // thread-in-group 0..3
    int wm   = wid & 3;     // warp m index
    int wn   = wid >> 2;    // warp n index == head
    int row0 = blockIdx.x * 128;
    int wrow = wm * 32;
    int wcol = wn * 64;

    if (t < 256) sAtt[t] = att[t];

    float c[2][8][4];
#pragma unroll
    for (int mt = 0; mt < 2; mt++)
#pragma unroll
        for (int nt = 0; nt < 8; nt++)
#pragma unroll
            for (int i = 0; i < 4; i++) c[mt][nt][i] = 0.f;

    for (int kc = 0; kc < K; kc += 32) {
#pragma unroll
        for (int it = 0; it < 4; it++) {
            int idx = t + it * 256;
            int r = idx >> 3;
            int q = idx & 7;
            int k = q * 4;

            float4 v = make_float4(0.f, 0.f, 0.f, 0.f);
            int grow = row0 + r;
            if (grow < N)
                v = *reinterpret_cast<const float4*>(X + (size_t)grow * K + kc + k);
            uint4 tv = make_uint4(f2tf32(v.x), f2tf32(v.y), f2tf32(v.z), f2tf32(v.w));
            *reinterpret_cast<uint4*>(&sX[r * TP + k]) = tv;

            float4 w = *reinterpret_cast<const float4*>(W + (size_t)r * K + kc + k);
            uint4 tw = make_uint4(f2tf32(w.x), f2tf32(w.y), f2tf32(w.z), f2tf32(w.w));
            *reinterpret_cast<uint4*>(&sW[r * TP + k]) = tw;
        }
        __syncthreads();

#pragma unroll
        for (int ks = 0; ks < 4; ks++) {
            int k0 = ks * 8;
            unsigned a[2][4];
#pragma unroll
            for (int mt = 0; mt < 2; mt++) {
                int r = wrow + mt * 16 + gid;
                a[mt][0] = sX[r * TP + k0 + tid];
                a[mt][1] = sX[(r + 8) * TP + k0 + tid];
                a[mt][2] = sX[r * TP + k0 + tid + 4];
                a[mt][3] = sX[(r + 8) * TP + k0 + tid + 4];
            }
            unsigned b[8][2];
#pragma unroll
            for (int nt = 0; nt < 8; nt++) {
                int n = wcol + nt * 8 + gid;
                b[nt][0] = sW[n * TP + k0 + tid];
                b[nt][1] = sW[n * TP + k0 + tid + 4];
            }
#pragma unroll
            for (int mt = 0; mt < 2; mt++)
#pragma unroll
                for (int nt = 0; nt < 8; nt++)
                    mma_tf32(c[mt][nt][0], c[mt][nt][1], c[mt][nt][2], c[mt][nt][3],
                             a[mt][0], a[mt][1], a[mt][2], a[mt][3],
                             b[nt][0], b[nt][1]);
        }
        __syncthreads();
    }

    float dp[2][2] = {{0.f, 0.f}, {0.f, 0.f}};
    float sp[2][2] = {{0.f, 0.f}, {0.f, 0.f}};

#pragma unroll
    for (int mt = 0; mt < 2; mt++) {
        int rlo = row0 + wrow + mt * 16 + gid;
        int rhi = rlo + 8;
#pragma unroll
        for (int nt = 0; nt < 8; nt++) {
            int cw = nt * 8 + tid * 2;
            int gc = wcol + cw;
            float c0 = c[mt][nt][0], c1 = c[mt][nt][1];
            float c2 = c[mt][nt][2], c3 = c[mt][nt][3];
            if (rlo < N)
                *reinterpret_cast<__half2*>(g_hh + (size_t)rlo * HC + gc) =
                    __floats2half2_rn(c0 * HSCALE, c1 * HSCALE);
            if (rhi < N)
                *reinterpret_cast<__half2*>(g_hh + (size_t)rhi * HC + gc) =
                    __floats2half2_rn(c2 * HSCALE, c3 * HSCALE);

            float ad0 = sAtt[wn * 128 + cw],      ad1 = sAtt[wn * 128 + cw + 1];
            float as0 = sAtt[wn * 128 + 64 + cw], as1 = sAtt[wn * 128 + 64 + cw + 1];
            dp[mt][0] = fmaf(c0, ad0, fmaf(c1, ad1, dp[mt][0]));
            sp[mt][0] = fmaf(c0, as0, fmaf(c1, as1, sp[mt][0]));
            dp[mt][1] = fmaf(c2, ad0, fmaf(c3, ad1, dp[mt][1]));
            sp[mt][1] = fmaf(c2, as0, fmaf(c3, as1, sp[mt][1]));
        }
    }
#pragma unroll
    for (int mt = 0; mt < 2; mt++)
#pragma unroll
        for (int u = 0; u < 2; u++) {
#pragma unroll
            for (int o = 1; o <= 2; o <<= 1) {
                dp[mt][u] += __shfl_xor_sync(0xffffffffu, dp[mt][u], o);
                sp[mt][u] += __shfl_xor_sync(0xffffffffu, sp[mt][u], o);
            }
            if (tid == 0) {
                int row = row0 + wrow + mt * 16 + gid + u * 8;
                if (row < N) {
                    g_sdst[row * 2 + wn] = dp[mt][u];
                    g_ssrc[row * 2 + wn] = sp[mt][u];
                }
            }
        }
}

// ---------------- gather: one warp per dst, inline alpha, scaled fp16 h -----
__global__ void __launch_bounds__(256) gather_kernel(
    int N, int layer, float* __restrict__ outp0,
    const float* __restrict__ bias, int doRelu, int toAcc)
{
    int wid  = (blockIdx.x * blockDim.x + threadIdx.x) >> 5;
    int lane = threadIdx.x & 31;
    if (wid >= N) return;
    int d = wid;

    float* outp = toAcc ? g_acc : outp0;

    int beg = g_roff[d];
    int end = g_roff[d + 1];

    // 0.5 = head mean; HSCALE_INV undoes fp16 storage scaling
    float inv0 = 0.5f * HSCALE_INV / (g_sum[layer * 2]     + 1e-10f);
    float inv1 = 0.5f * HSCALE_INV / (g_sum[layer * 2 + 1] + 1e-10f);

    float2 scd = *reinterpret_cast<const float2*>(g_sdst + d * 2);

    const uint2* hv = reinterpret_cast<const uint2*>(g_hh);
    float4 acc = make_float4(0.f, 0.f, 0.f, 0.f);

    for (int base = beg; base < end; base += 32) {
        int idx = base + lane;
        int   s   = 0;
        float aw0 = 0.f, aw1 = 0.f;
        if (idx < end) {
            s = g_csr[idx];
            float2 scs = *reinterpret_cast<const float2*>(g_ssrc + s * 2);
            aw0 = lrexp(scd.x + scs.x) * inv0;
            aw1 = lrexp(scd.y + scs.y) * inv1;
        }
        int cnt = min(32, end - base);
#pragma unroll 4
        for (int j = 0; j < cnt; j++) {
            int   sj = __shfl_sync(0xffffffffu, s,   j);
            float w0 = __shfl_sync(0xffffffffu, aw0, j);
            float w1 = __shfl_sync(0xffffffffu, aw1, j);
            float ww = (lane < 16) ? w0 : w1;
            uint2 raw = hv[(size_t)sj * 32 + lane];   // 4 halves
            float2 f01 = __half22float2(*reinterpret_cast<__half2*>(&raw.x));
            float2 f23 = __half22float2(*reinterpret_cast<__half2*>(&raw.y));
            acc.x = fmaf(ww, f01.x, acc.x);
            acc.y = fmaf(ww, f01.y, acc.y);
            acc.z = fmaf(ww, f23.x, acc.z);
            acc.w = fmaf(ww, f23.y, acc.w);
        }
    }

    acc.x += __shfl_xor_sync(0xffffffffu, acc.x, 16);
    acc.y += __shfl_xor_sync(0xffffffffu, acc.y, 16);
    acc.z += __shfl_xor_sync(0xffffffffu, acc.z, 16);
    acc.w += __shfl_xor_sync(0xffffffffu, acc.w, 16);

    if (lane < 16) {
        const float4 b = reinterpret_cast<const float4*>(bias)[lane];
        acc.x += b.x; acc.y += b.y; acc.z += b.z; acc.w += b.w;
        if (doRelu) {
            acc.x = fmaxf(acc.x, 0.f);
            acc.y = fmaxf(acc.y, 0.f);
            acc.z = fmaxf(acc.z, 0.f);
            acc.w = fmaxf(acc.w, 0.f);
        }
        reinterpret_cast<float4*>(outp + (size_t)d * CD)[lane] = acc;
    }
}

// ---------------- launch ----------------
extern "C" void kernel_launch(void* const* d_in, const int* in_sizes, int n_in,
                              void* d_out, int out_size)
{
    const float* x    = (const float*)d_in[0];
    const int*   ei32 = (const int*)d_in[1];
    const float* W1   = (const float*)d_in[2];
    const float* att1 = (const float*)d_in[3];
    const float* b1   = (const float*)d_in[4];
    const float* W2   = (const float*)d_in[5];
    const float* att2 = (const float*)d_in[6];
    const float* b2   = (const float*)d_in[7];
    float* out = (float*)d_out;

    int N  = in_sizes[0] / FIN;
    int E  = in_sizes[1] / 2;
    int ET = E + N;
    int nb = (N + SCAN_CHUNK - 1) / SCAN_CHUNK;

    init_detect_kernel<<<(N + 255) / 256, 256>>>(ei32, E, N);
    gemm_tc_kernel<FIN><<<(N + 127) / 128, 256>>>(x, 0, W1, att1, N);
    hist_kernel<<<(E + 255) / 256, 256>>>(ei32, E);
    partial_kernel<<<nb, 256>>>(N);
    scanp_kernel<<<1, 256>>>(nb, N);
    offsets_kernel<<<nb, 256>>>(N);
    scatter_sum_kernel<<<(ET + 255) / 256, 256>>>(ei32, E, N);

    // ---- layer 1 ----
    gather_kernel<<<(N * 32 + 255) / 256, 256>>>(N, 0, out, b1, 1, 1);

    // ---- layer 2 ----
    gemm_tc_kernel<CD><<<(N + 127) / 128, 256>>>(x /*unused*/, 1, W2, att2, N);
    sum2_kernel<<<(ET + 255) / 256, 256>>>(ei32, E, N);
    gather_kernel<<<(N * 32 + 255) / 256, 256>>>(N, 1, out, b2, 0, 0);
}

// round 9
// speedup vs baseline: 2.4688x; 1.0234x over previous
#include <cuda_runtime.h>
#include <cuda_fp16.h>
#include <math.h>

// Problem constants (shapes fixed by the dataset)
#define HC   128      // HEADS * C
#define CD   64       // C
#define FIN  128      // Fin of layer 1
#define NMAX 50048
#define EMAX 800256
#define ETMAX (NMAX + EMAX)
#define SCAN_CHUNK 2048   // elements per scan block (256 thr x 8)
#define HSCALE 4096.0f    // fp16 storage scale (keeps layer-2 h out of subnormals)
#define HSCALE_INV (1.0f / 4096.0f)

// ---------------- scratch (device globals; no allocation) ----------------
__device__ __align__(16) __half g_hh[(size_t)NMAX * HC];    // GEMM output * HSCALE, fp16
__device__ __align__(16) float  g_acc[(size_t)NMAX * CD];   // layer-1 out / layer-2 input (fp32)
__device__ __align__(8)  float  g_sdst[NMAX * 2];           // per-node dst-scores [N,H]
__device__ __align__(8)  float  g_ssrc[NMAX * 2];           // per-node src-scores [N,H]
__device__ float    g_sum[4];                   // per-layer per-head exp sums
// CSR (built once per launch; edges identical for both layers)
// g_deg convention: stores EXTRA in-degree (self-loop excluded); zero-init,
// and offsets_kernel resets it to 0 after use -> replay-clean without init pass.
__device__ int      g_deg[NMAX];
__device__ int      g_roff[NMAX + 1];
__device__ int      g_cursor[NMAX];
__device__ int      g_csr[ETMAX];               // src per incoming edge (dst-sorted)
__device__ int      g_bsum[256];                // per-block degree sums

__device__ __forceinline__ unsigned f2tf32(float f) {
    unsigned r;
    asm("cvt.rna.tf32.f32 %0, %1;" : "=r"(r) : "f"(f));
    return r;
}

__device__ __forceinline__ void mma_tf32(
    float& c0, float& c1, float& c2, float& c3,
    unsigned a0, unsigned a1, unsigned a2, unsigned a3,
    unsigned b0, unsigned b1)
{
    asm volatile(
        "mma.sync.aligned.m16n8k8.row.col.f32.tf32.tf32.f32 "
        "{%0,%1,%2,%3}, {%4,%5,%6,%7}, {%8,%9}, {%0,%1,%2,%3};"
        : "+f"(c0), "+f"(c1), "+f"(c2), "+f"(c3)
        : "r"(a0), "r"(a1), "r"(a2), "r"(a3), "r"(b0), "r"(b1));
}

// per-block dtype detection: int64 edges (<2^31) have all-zero odd words.
// Computed by thread 0, shared with the block. Returns 1 if int32 payload.
__device__ __forceinline__ int block_detect_is32(const int* __restrict__ ei32) {
    __shared__ int sIs32;
    if (threadIdx.x == 0) {
        unsigned v = 0;
#pragma unroll
        for (int i = 0; i < 32; i++) v |= (unsigned)ei32[2 * i + 1];
        sIs32 = (v != 0u) ? 1 : 0;
    }
    __syncthreads();
    return sIs32;
}

__device__ __forceinline__ void load_edge(const int* __restrict__ ei32,
                                          int e, int E, int is32, int& s, int& d) {
    if (is32) { s = ei32[e];     d = ei32[E + e]; }
    else      { s = ei32[2 * e]; d = ei32[2 * (E + e)]; }
}

// leaky-relu(0.2) then exp
__device__ __forceinline__ float lrexp(float a) {
    a = (a >= 0.f) ? a : 0.2f * a;
    return __expf(a);
}

// ---------------- CSR build ----------------
// histogram of extra in-degree; also resets g_sum for this pass
__global__ void __launch_bounds__(256) hist_kernel(const int* __restrict__ ei32, int E) {
    int is32 = block_detect_is32(ei32);
    int e = blockIdx.x * blockDim.x + threadIdx.x;
    if (blockIdx.x == 0 && threadIdx.x < 4) g_sum[threadIdx.x] = 0.f;
    if (e < E) {
        int s, d;
        load_edge(ei32, e, E, is32, s, d);
        atomicAdd(&g_deg[d], 1);
    }
}

__global__ void __launch_bounds__(256) partial_kernel(int N) {
    __shared__ int sT[256];
    int b = blockIdx.x, t = threadIdx.x;
    int beg = b * SCAN_CHUNK + t * 8;
    int s = 0;
#pragma unroll
    for (int i = 0; i < 8; i++) {
        int idx = beg + i;
        if (idx < N) s += g_deg[idx] + 1;   // +1 self loop
    }
    sT[t] = s;
    __syncthreads();
#pragma unroll
    for (int off = 128; off > 0; off >>= 1) {
        if (t < off) sT[t] += sT[t + off];
        __syncthreads();
    }
    if (t == 0) g_bsum[b] = sT[0];
}

// offsets: inline scan of <=256 block sums + local scan + deg reset
__global__ void __launch_bounds__(256) offsets_kernel(int N, int nb) {
    __shared__ int sT[256];
    __shared__ int sBase;
    int b = blockIdx.x, t = threadIdx.x;

    if (t == 0) {
        int base = 0;
        for (int j = 0; j < b; j++) base += g_bsum[j];
        sBase = base;
        if (b == 0) {
            int total = 0;
            for (int j = 0; j < nb; j++) total += g_bsum[j];
            g_roff[N] = total;
        }
    }

    int beg = b * SCAN_CHUNK + t * 8;
    int v[8];
    int s = 0;
#pragma unroll
    for (int i = 0; i < 8; i++) {
        int idx = beg + i;
        v[i] = (idx < N) ? (g_deg[idx] + 1) : 0;
        s += v[i];
    }
    sT[t] = s;
    __syncthreads();
    for (int off = 1; off < 256; off <<= 1) {
        int x = (t >= off) ? sT[t - off] : 0;
        __syncthreads();
        sT[t] += x;
        __syncthreads();
    }
    int excl = ((t == 0) ? 0 : sT[t - 1]) + sBase;
#pragma unroll
    for (int i = 0; i < 8; i++) {
        int idx = beg + i;
        if (idx < N) {
            g_roff[idx]   = excl;
            g_cursor[idx] = excl;
            g_deg[idx]    = 0;          // replay-clean reset
            excl += v[i];
        }
    }
}

// scatter to CSR + fused layer-0 softmax-denominator sums (scores ready: gemm1 ran)
__global__ void __launch_bounds__(256) scatter_sum_kernel(
    const int* __restrict__ ei32, int E, int N)
{
    int is32 = block_detect_is32(ei32);
    int e = blockIdx.x * blockDim.x + threadIdx.x;
    int ET = E + N;
    float s0 = 0.f, s1 = 0.f;
    if (e < ET) {
        int s, d;
        if (e < E) load_edge(ei32, e, E, is32, s, d);
        else       s = d = e - E;
        int pos = atomicAdd(&g_cursor[d], 1);
        g_csr[pos] = s;
        s0 = lrexp(g_sdst[d * 2]     + g_ssrc[s * 2]);
        s1 = lrexp(g_sdst[d * 2 + 1] + g_ssrc[s * 2 + 1]);
    }
#pragma unroll
    for (int o = 16; o > 0; o >>= 1) {
        s0 += __shfl_xor_sync(0xffffffffu, s0, o);
        s1 += __shfl_xor_sync(0xffffffffu, s1, o);
    }
    __shared__ float sm0[8], sm1[8];
    if ((threadIdx.x & 31) == 0) {
        sm0[threadIdx.x >> 5] = s0;
        sm1[threadIdx.x >> 5] = s1;
    }
    __syncthreads();
    if (threadIdx.x == 0) {
        float t0 = 0.f, t1 = 0.f;
#pragma unroll
        for (int i = 0; i < 8; i++) { t0 += sm0[i]; t1 += sm1[i]; }
        atomicAdd(&g_sum[0], t0);
        atomicAdd(&g_sum[1], t1);
    }
}

// layer-2 softmax-denominator sums only
__global__ void __launch_bounds__(256) sum2_kernel(
    const int* __restrict__ ei32, int E, int N)
{
    int is32 = block_detect_is32(ei32);
    int e = blockIdx.x * blockDim.x + threadIdx.x;
    int ET = E + N;
    float s0 = 0.f, s1 = 0.f;
    if (e < ET) {
        int s, d;
        if (e < E) load_edge(ei32, e, E, is32, s, d);
        else       s = d = e - E;
        s0 = lrexp(g_sdst[d * 2]     + g_ssrc[s * 2]);
        s1 = lrexp(g_sdst[d * 2 + 1] + g_ssrc[s * 2 + 1]);
    }
#pragma unroll
    for (int o = 16; o > 0; o >>= 1) {
        s0 += __shfl_xor_sync(0xffffffffu, s0, o);
        s1 += __shfl_xor_sync(0xffffffffu, s1, o);
    }
    __shared__ float sm0[8], sm1[8];
    if ((threadIdx.x & 31) == 0) {
        sm0[threadIdx.x >> 5] = s0;
        sm1[threadIdx.x >> 5] = s1;
    }
    __syncthreads();
    if (threadIdx.x == 0) {
        float t0 = 0.f, t1 = 0.f;
#pragma unroll
        for (int i = 0; i < 8; i++) { t0 += sm0[i]; t1 += sm1[i]; }
        atomicAdd(&g_sum[2], t0);
        atomicAdd(&g_sum[3], t1);
    }
}

// ---------------- tf32 tensor-core GEMM + fused score epilogue --------------
#define TP 36   // smem pitch (32 k + 4 pad) -> conflict-free fragment loads

template <int K>
__global__ void __launch_bounds__(256) gemm_tc_kernel(
    const float* __restrict__ X0, int useAcc,
    const float* __restrict__ W, const float* __restrict__ att, int N)
{
    __shared__ __align__(16) unsigned sX[128 * TP];
    __shared__ __align__(16) unsigned sW[128 * TP];
    __shared__ float sAtt[256];

    const float* X = useAcc ? g_acc : X0;

    int t    = threadIdx.x;
    int wid  = t >> 5;
    int lane = t & 31;
    int gid  = lane >> 2;   // group id 0..7
    int tid  = lane & 3;    // thread-in-group 0..3
    int wm   = wid & 3;     // warp m index
    int wn   = wid >> 2;    // warp n index == head
    int row0 = blockIdx.x * 128;
    int wrow = wm * 32;
    int wcol = wn * 64;

    if (t < 256) sAtt[t] = att[t];

    float c[2][8][4];
#pragma unroll
    for (int mt = 0; mt < 2; mt++)
#pragma unroll
        for (int nt = 0; nt < 8; nt++)
#pragma unroll
            for (int i = 0; i < 4; i++) c[mt][nt][i] = 0.f;

    for (int kc = 0; kc < K; kc += 32) {
#pragma unroll
        for (int it = 0; it < 4; it++) {
            int idx = t + it * 256;
            int r = idx >> 3;
            int q = idx & 7;
            int k = q * 4;

            float4 v = make_float4(0.f, 0.f, 0.f, 0.f);
            int grow = row0 + r;
            if (grow < N)
                v = *reinterpret_cast<const float4*>(X + (size_t)grow * K + kc + k);
            uint4 tv = make_uint4(f2tf32(v.x), f2tf32(v.y), f2tf32(v.z), f2tf32(v.w));
            *reinterpret_cast<uint4*>(&sX[r * TP + k]) = tv;

            float4 w = *reinterpret_cast<const float4*>(W + (size_t)r * K + kc + k);
            uint4 tw = make_uint4(f2tf32(w.x), f2tf32(w.y), f2tf32(w.z), f2tf32(w.w));
            *reinterpret_cast<uint4*>(&sW[r * TP + k]) = tw;
        }
        __syncthreads();

#pragma unroll
        for (int ks = 0; ks < 4; ks++) {
            int k0 = ks * 8;
            unsigned a[2][4];
#pragma unroll
            for (int mt = 0; mt < 2; mt++) {
                int r = wrow + mt * 16 + gid;
                a[mt][0] = sX[r * TP + k0 + tid];
                a[mt][1] = sX[(r + 8) * TP + k0 + tid];
                a[mt][2] = sX[r * TP + k0 + tid + 4];
                a[mt][3] = sX[(r + 8) * TP + k0 + tid + 4];
            }
            unsigned b[8][2];
#pragma unroll
            for (int nt = 0; nt < 8; nt++) {
                int n = wcol + nt * 8 + gid;
                b[nt][0] = sW[n * TP + k0 + tid];
                b[nt][1] = sW[n * TP + k0 + tid + 4];
            }
#pragma unroll
            for (int mt = 0; mt < 2; mt++)
#pragma unroll
                for (int nt = 0; nt < 8; nt++)
                    mma_tf32(c[mt][nt][0], c[mt][nt][1], c[mt][nt][2], c[mt][nt][3],
                             a[mt][0], a[mt][1], a[mt][2], a[mt][3],
                             b[nt][0], b[nt][1]);
        }
        __syncthreads();
    }

    float dp[2][2] = {{0.f, 0.f}, {0.f, 0.f}};
    float sp[2][2] = {{0.f, 0.f}, {0.f, 0.f}};

#pragma unroll
    for (int mt = 0; mt < 2; mt++) {
        int rlo = row0 + wrow + mt * 16 + gid;
        int rhi = rlo + 8;
#pragma unroll
        for (int nt = 0; nt < 8; nt++) {
            int cw = nt * 8 + tid * 2;
            int gc = wcol + cw;
            float c0 = c[mt][nt][0], c1 = c[mt][nt][1];
            float c2 = c[mt][nt][2], c3 = c[mt][nt][3];
            if (rlo < N)
                *reinterpret_cast<__half2*>(g_hh + (size_t)rlo * HC + gc) =
                    __floats2half2_rn(c0 * HSCALE, c1 * HSCALE);
            if (rhi < N)
                *reinterpret_cast<__half2*>(g_hh + (size_t)rhi * HC + gc) =
                    __floats2half2_rn(c2 * HSCALE, c3 * HSCALE);

            float ad0 = sAtt[wn * 128 + cw],      ad1 = sAtt[wn * 128 + cw + 1];
            float as0 = sAtt[wn * 128 + 64 + cw], as1 = sAtt[wn * 128 + 64 + cw + 1];
            dp[mt][0] = fmaf(c0, ad0, fmaf(c1, ad1, dp[mt][0]));
            sp[mt][0] = fmaf(c0, as0, fmaf(c1, as1, sp[mt][0]));
            dp[mt][1] = fmaf(c2, ad0, fmaf(c3, ad1, dp[mt][1]));
            sp[mt][1] = fmaf(c2, as0, fmaf(c3, as1, sp[mt][1]));
        }
    }
#pragma unroll
    for (int mt = 0; mt < 2; mt++)
#pragma unroll
        for (int u = 0; u < 2; u++) {
#pragma unroll
            for (int o = 1; o <= 2; o <<= 1) {
                dp[mt][u] += __shfl_xor_sync(0xffffffffu, dp[mt][u], o);
                sp[mt][u] += __shfl_xor_sync(0xffffffffu, sp[mt][u], o);
            }
            if (tid == 0) {
                int row = row0 + wrow + mt * 16 + gid + u * 8;
                if (row < N) {
                    g_sdst[row * 2 + wn] = dp[mt][u];
                    g_ssrc[row * 2 + wn] = sp[mt][u];
                }
            }
        }
}

// ---------------- gather: one warp per dst, inline alpha, scaled fp16 h -----
__global__ void __launch_bounds__(256) gather_kernel(
    int N, int layer, float* __restrict__ outp0,
    const float* __restrict__ bias, int doRelu, int toAcc)
{
    int wid  = (blockIdx.x * blockDim.x + threadIdx.x) >> 5;
    int lane = threadIdx.x & 31;
    if (wid >= N) return;
    int d = wid;

    float* outp = toAcc ? g_acc : outp0;

    int beg = g_roff[d];
    int end = g_roff[d + 1];

    // 0.5 = head mean; HSCALE_INV undoes fp16 storage scaling
    float inv0 = 0.5f * HSCALE_INV / (g_sum[layer * 2]     + 1e-10f);
    float inv1 = 0.5f * HSCALE_INV / (g_sum[layer * 2 + 1] + 1e-10f);

    float2 scd = *reinterpret_cast<const float2*>(g_sdst + d * 2);

    const uint2* hv = reinterpret_cast<const uint2*>(g_hh);
    float4 acc = make_float4(0.f, 0.f, 0.f, 0.f);

    for (int base = beg; base < end; base += 32) {
        int idx = base + lane;
        int   s   = 0;
        float aw0 = 0.f, aw1 = 0.f;
        if (idx < end) {
            s = g_csr[idx];
            float2 scs = *reinterpret_cast<const float2*>(g_ssrc + s * 2);
            aw0 = lrexp(scd.x + scs.x) * inv0;
            aw1 = lrexp(scd.y + scs.y) * inv1;
        }
        int cnt = min(32, end - base);
#pragma unroll 4
        for (int j = 0; j < cnt; j++) {
            int   sj = __shfl_sync(0xffffffffu, s,   j);
            float w0 = __shfl_sync(0xffffffffu, aw0, j);
            float w1 = __shfl_sync(0xffffffffu, aw1, j);
            float ww = (lane < 16) ? w0 : w1;
            uint2 raw = hv[(size_t)sj * 32 + lane];   // 4 halves
            float2 f01 = __half22float2(*reinterpret_cast<__half2*>(&raw.x));
            float2 f23 = __half22float2(*reinterpret_cast<__half2*>(&raw.y));
            acc.x = fmaf(ww, f01.x, acc.x);
            acc.y = fmaf(ww, f01.y, acc.y);
            acc.z = fmaf(ww, f23.x, acc.z);
            acc.w = fmaf(ww, f23.y, acc.w);
        }
    }

    acc.x += __shfl_xor_sync(0xffffffffu, acc.x, 16);
    acc.y += __shfl_xor_sync(0xffffffffu, acc.y, 16);
    acc.z += __shfl_xor_sync(0xffffffffu, acc.z, 16);
    acc.w += __shfl_xor_sync(0xffffffffu, acc.w, 16);

    if (lane < 16) {
        const float4 b = reinterpret_cast<const float4*>(bias)[lane];
        acc.x += b.x; acc.y += b.y; acc.z += b.z; acc.w += b.w;
        if (doRelu) {
            acc.x = fmaxf(acc.x, 0.f);
            acc.y = fmaxf(acc.y, 0.f);
            acc.z = fmaxf(acc.z, 0.f);
            acc.w = fmaxf(acc.w, 0.f);
        }
        reinterpret_cast<float4*>(outp + (size_t)d * CD)[lane] = acc;
    }
}

// ---------------- launch ----------------
extern "C" void kernel_launch(void* const* d_in, const int* in_sizes, int n_in,
                              void* d_out, int out_size)
{
    const float* x    = (const float*)d_in[0];
    const int*   ei32 = (const int*)d_in[1];
    const float* W1   = (const float*)d_in[2];
    const float* att1 = (const float*)d_in[3];
    const float* b1   = (const float*)d_in[4];
    const float* W2   = (const float*)d_in[5];
    const float* att2 = (const float*)d_in[6];
    const float* b2   = (const float*)d_in[7];
    float* out = (float*)d_out;

    int N  = in_sizes[0] / FIN;
    int E  = in_sizes[1] / 2;
    int ET = E + N;
    int nb = (N + SCAN_CHUNK - 1) / SCAN_CHUNK;

    // launch order also places gather1 at index 5 for ncu -s 5 -c 1
    gemm_tc_kernel<FIN><<<(N + 127) / 128, 256>>>(x, 0, W1, att1, N);   // 1
    hist_kernel<<<(E + 255) / 256, 256>>>(ei32, E);                     // 2
    partial_kernel<<<nb, 256>>>(N);                                     // 3
    offsets_kernel<<<nb, 256>>>(N, nb);                                 // 4
    scatter_sum_kernel<<<(ET + 255) / 256, 256>>>(ei32, E, N);          // 5
    gather_kernel<<<(N * 32 + 255) / 256, 256>>>(N, 0, out, b1, 1, 1);  // 6 <- profiled
    gemm_tc_kernel<CD><<<(N + 127) / 128, 256>>>(x /*unused*/, 1, W2, att2, N); // 7
    sum2_kernel<<<(ET + 255) / 256, 256>>>(ei32, E, N);                 // 8
    gather_kernel<<<(N * 32 + 255) / 256, 256>>>(N, 1, out, b2, 0, 0);  // 9
}

// round 10
// speedup vs baseline: 2.7375x; 1.1088x over previous
#include <cuda_runtime.h>
#include <cuda_fp16.h>
#include <math.h>

// Problem constants (shapes fixed by the dataset)
#define HC   128      // HEADS * C
#define CD   64       // C
#define FIN  128      // Fin of layer 1
#define NMAX 50048
#define EMAX 800256
#define ETMAX (NMAX + EMAX)
#define SCAN_CHUNK 2048   // elements per scan block (256 thr x 8)
#define HSCALE 4096.0f    // fp16 storage scale (keeps layer-2 h out of subnormals)
#define HSCALE_INV (1.0f / 4096.0f)

// ---------------- scratch (device globals; no allocation) ----------------
__device__ __align__(16) __half g_hh[(size_t)NMAX * HC];    // GEMM output * HSCALE, fp16
__device__ __align__(16) float  g_acc[(size_t)NMAX * CD];   // layer-1 out / layer-2 input
__device__ __align__(8)  float  g_sdst[NMAX * 2];           // per-node dst-scores [N,H]
__device__ __align__(8)  float  g_ssrc[NMAX * 2];           // per-node src-scores [N,H]
__device__ float    g_sum[4];                   // per-layer per-head exp sums
// CSR: g_deg stores EXTRA in-degree (self-loop excluded); zero-init and
// reset-after-use by offsets_kernel -> replay-clean with no init pass.
__device__ __align__(16) int g_deg[NMAX];
__device__ __align__(16) int g_roff[NMAX + 8];
__device__ __align__(16) int g_cursor[NMAX];
__device__ int      g_csr[ETMAX];               // src per incoming edge (dst-sorted)
__device__ int      g_bsum[256];                // per-block degree sums

__device__ __forceinline__ unsigned f2tf32(float f) {
    unsigned r;
    asm("cvt.rna.tf32.f32 %0, %1;" : "=r"(r) : "f"(f));
    return r;
}

__device__ __forceinline__ void mma_tf32(
    float& c0, float& c1, float& c2, float& c3,
    unsigned a0, unsigned a1, unsigned a2, unsigned a3,
    unsigned b0, unsigned b1)
{
    asm volatile(
        "mma.sync.aligned.m16n8k8.row.col.f32.tf32.tf32.f32 "
        "{%0,%1,%2,%3}, {%4,%5,%6,%7}, {%8,%9}, {%0,%1,%2,%3};"
        : "+f"(c0), "+f"(c1), "+f"(c2), "+f"(c3)
        : "r"(a0), "r"(a1), "r"(a2), "r"(a3), "r"(b0), "r"(b1));
}

// per-block dtype detection: int64 edges (<2^31) have all-zero odd words.
__device__ __forceinline__ int block_detect_is32(const int* __restrict__ ei32) {
    __shared__ int sIs32;
    if (threadIdx.x == 0) {
        unsigned v = 0;
#pragma unroll
        for (int i = 0; i < 32; i++) v |= (unsigned)ei32[2 * i + 1];
        sIs32 = (v != 0u) ? 1 : 0;
    }
    __syncthreads();
    return sIs32;
}

__device__ __forceinline__ void load_edge(const int* __restrict__ ei32,
                                          int e, int E, int is32, int& s, int& d) {
    if (is32) { s = ei32[e];     d = ei32[E + e]; }
    else      { s = ei32[2 * e]; d = ei32[2 * (E + e)]; }
}

__device__ __forceinline__ float lrexp(float a) {
    a = (a >= 0.f) ? a : 0.2f * a;
    return __expf(a);
}

// ---------------- tf32 tensor-core GEMM + fused score epilogue --------------
// Blocks [0, nGemm) do the GEMM; blocks >= nGemm run the degree histogram
// (independent work, overlapped in one launch; pass nHistE=0 to disable).
#define TP 36   // smem pitch (32 k + 4 pad) -> conflict-free fragment loads

template <int K>
__global__ void __launch_bounds__(256) gemm_tc_kernel(
    const float* __restrict__ X0, int useAcc,
    const float* __restrict__ W, const float* __restrict__ att, int N,
    const int* __restrict__ ei32, int nHistE, int nGemm)
{
    // ---- histogram part (layer-1 launch only) ----
    if (blockIdx.x >= (unsigned)nGemm) {
        int hb = blockIdx.x - nGemm;
        int is32 = block_detect_is32(ei32);
        if (hb == 0 && threadIdx.x < 4) g_sum[threadIdx.x] = 0.f;
        int e = hb * 256 + threadIdx.x;
        if (e < nHistE) {
            int s, d;
            load_edge(ei32, e, nHistE, is32, s, d);
            atomicAdd(&g_deg[d], 1);
        }
        return;
    }

    __shared__ __align__(16) unsigned sX[128 * TP];
    __shared__ __align__(16) unsigned sW[128 * TP];
    __shared__ float sAtt[256];

    const float* X = useAcc ? g_acc : X0;

    int t    = threadIdx.x;
    int wid  = t >> 5;
    int lane = t & 31;
    int gid  = lane >> 2;
    int tid  = lane & 3;
    int wm   = wid & 3;
    int wn   = wid >> 2;    // head
    int row0 = blockIdx.x * 128;
    int wrow = wm * 32;
    int wcol = wn * 64;

    if (t < 256) sAtt[t] = att[t];

    float c[2][8][4];
#pragma unroll
    for (int mt = 0; mt < 2; mt++)
#pragma unroll
        for (int nt = 0; nt < 8; nt++)
#pragma unroll
            for (int i = 0; i < 4; i++) c[mt][nt][i] = 0.f;

    for (int kc = 0; kc < K; kc += 32) {
#pragma unroll
        for (int it = 0; it < 4; it++) {
            int idx = t + it * 256;
            int r = idx >> 3;
            int q = idx & 7;
            int k = q * 4;

            float4 v = make_float4(0.f, 0.f, 0.f, 0.f);
            int grow = row0 + r;
            if (grow < N)
                v = *reinterpret_cast<const float4*>(X + (size_t)grow * K + kc + k);
            uint4 tv = make_uint4(f2tf32(v.x), f2tf32(v.y), f2tf32(v.z), f2tf32(v.w));
            *reinterpret_cast<uint4*>(&sX[r * TP + k]) = tv;

            float4 w = *reinterpret_cast<const float4*>(W + (size_t)r * K + kc + k);
            uint4 tw = make_uint4(f2tf32(w.x), f2tf32(w.y), f2tf32(w.z), f2tf32(w.w));
            *reinterpret_cast<uint4*>(&sW[r * TP + k]) = tw;
        }
        __syncthreads();

#pragma unroll
        for (int ks = 0; ks < 4; ks++) {
            int k0 = ks * 8;
            unsigned a[2][4];
#pragma unroll
            for (int mt = 0; mt < 2; mt++) {
                int r = wrow + mt * 16 + gid;
                a[mt][0] = sX[r * TP + k0 + tid];
                a[mt][1] = sX[(r + 8) * TP + k0 + tid];
                a[mt][2] = sX[r * TP + k0 + tid + 4];
                a[mt][3] = sX[(r + 8) * TP + k0 + tid + 4];
            }
            unsigned b[8][2];
#pragma unroll
            for (int nt = 0; nt < 8; nt++) {
                int n = wcol + nt * 8 + gid;
                b[nt][0] = sW[n * TP + k0 + tid];
                b[nt][1] = sW[n * TP + k0 + tid + 4];
            }
#pragma unroll
            for (int mt = 0; mt < 2; mt++)
#pragma unroll
                for (int nt = 0; nt < 8; nt++)
                    mma_tf32(c[mt][nt][0], c[mt][nt][1], c[mt][nt][2], c[mt][nt][3],
                             a[mt][0], a[mt][1], a[mt][2], a[mt][3],
                             b[nt][0], b[nt][1]);
        }
        __syncthreads();
    }

    float dp[2][2] = {{0.f, 0.f}, {0.f, 0.f}};
    float sp[2][2] = {{0.f, 0.f}, {0.f, 0.f}};

#pragma unroll
    for (int mt = 0; mt < 2; mt++) {
        int rlo = row0 + wrow + mt * 16 + gid;
        int rhi = rlo + 8;
#pragma unroll
        for (int nt = 0; nt < 8; nt++) {
            int cw = nt * 8 + tid * 2;
            int gc = wcol + cw;
            float c0 = c[mt][nt][0], c1 = c[mt][nt][1];
            float c2 = c[mt][nt][2], c3 = c[mt][nt][3];
            if (rlo < N)
                *reinterpret_cast<__half2*>(g_hh + (size_t)rlo * HC + gc) =
                    __floats2half2_rn(c0 * HSCALE, c1 * HSCALE);
            if (rhi < N)
                *reinterpret_cast<__half2*>(g_hh + (size_t)rhi * HC + gc) =
                    __floats2half2_rn(c2 * HSCALE, c3 * HSCALE);

            float ad0 = sAtt[wn * 128 + cw],      ad1 = sAtt[wn * 128 + cw + 1];
            float as0 = sAtt[wn * 128 + 64 + cw], as1 = sAtt[wn * 128 + 64 + cw + 1];
            dp[mt][0] = fmaf(c0, ad0, fmaf(c1, ad1, dp[mt][0]));
            sp[mt][0] = fmaf(c0, as0, fmaf(c1, as1, sp[mt][0]));
            dp[mt][1] = fmaf(c2, ad0, fmaf(c3, ad1, dp[mt][1]));
            sp[mt][1] = fmaf(c2, as0, fmaf(c3, as1, sp[mt][1]));
        }
    }
#pragma unroll
    for (int mt = 0; mt < 2; mt++)
#pragma unroll
        for (int u = 0; u < 2; u++) {
#pragma unroll
            for (int o = 1; o <= 2; o <<= 1) {
                dp[mt][u] += __shfl_xor_sync(0xffffffffu, dp[mt][u], o);
                sp[mt][u] += __shfl_xor_sync(0xffffffffu, sp[mt][u], o);
            }
            if (tid == 0) {
                int row = row0 + wrow + mt * 16 + gid + u * 8;
                if (row < N) {
                    g_sdst[row * 2 + wn] = dp[mt][u];
                    g_ssrc[row * 2 + wn] = sp[mt][u];
                }
            }
        }
}

// ---------------- scan phase 1: per-block sums (vectorized, warp reduce) ----
__global__ void __launch_bounds__(256) partial_kernel(int N) {
    int b = blockIdx.x, t = threadIdx.x;
    int beg = b * SCAN_CHUNK + t * 8;
    int s = 0;
    if (beg + 8 <= N) {
        int4 a = *reinterpret_cast<const int4*>(g_deg + beg);
        int4 c = *reinterpret_cast<const int4*>(g_deg + beg + 4);
        s = a.x + a.y + a.z + a.w + c.x + c.y + c.z + c.w + 8;
    } else {
#pragma unroll
        for (int i = 0; i < 8; i++) {
            int idx = beg + i;
            if (idx < N) s += g_deg[idx] + 1;
        }
    }
    s = __reduce_add_sync(0xffffffffu, s);
    __shared__ int wsum[8];
    if ((t & 31) == 0) wsum[t >> 5] = s;
    __syncthreads();
    if (t == 0) {
        int tot = 0;
#pragma unroll
        for (int i = 0; i < 8; i++) tot += wsum[i];
        g_bsum[b] = tot;
    }
}

// ---------------- scan phase 2: offsets (warp-shuffle scan, vectorized) -----
__global__ void __launch_bounds__(256) offsets_kernel(int N, int nb) {
    __shared__ int sBase;
    __shared__ int wsum[8];
    int b = blockIdx.x, t = threadIdx.x;
    int lane = t & 31, w = t >> 5;

    if (t < 32) {
        int val = (t < nb) ? g_bsum[t] : 0;
        int base = __reduce_add_sync(0xffffffffu, (t < b) ? val : 0);
        if (t == 0) {
            sBase = base;
            if (b == 0) {
                // total for g_roff[N]
            }
        }
        if (b == 0) {
            int total = __reduce_add_sync(0xffffffffu, val);
            if (t == 0) g_roff[N] = total;
        }
    }

    int beg = b * SCAN_CHUNK + t * 8;
    int v[8];
    int s;
    bool vec = (beg + 8 <= N);
    if (vec) {
        int4 a = *reinterpret_cast<const int4*>(g_deg + beg);
        int4 c = *reinterpret_cast<const int4*>(g_deg + beg + 4);
        v[0] = a.x + 1; v[1] = a.y + 1; v[2] = a.z + 1; v[3] = a.w + 1;
        v[4] = c.x + 1; v[5] = c.y + 1; v[6] = c.z + 1; v[7] = c.w + 1;
        int4 z = make_int4(0, 0, 0, 0);
        *reinterpret_cast<int4*>(g_deg + beg)     = z;   // replay-clean reset
        *reinterpret_cast<int4*>(g_deg + beg + 4) = z;
    } else {
#pragma unroll
        for (int i = 0; i < 8; i++) {
            int idx = beg + i;
            v[i] = (idx < N) ? (g_deg[idx] + 1) : 0;
            if (idx < N) g_deg[idx] = 0;
        }
    }
    s = v[0] + v[1] + v[2] + v[3] + v[4] + v[5] + v[6] + v[7];

    // warp inclusive scan of per-thread sums
    int ps = s;
#pragma unroll
    for (int o = 1; o < 32; o <<= 1) {
        int x = __shfl_up_sync(0xffffffffu, ps, o);
        if (lane >= o) ps += x;
    }
    if (lane == 31) wsum[w] = ps;
    __syncthreads();
    int wbase = 0;
#pragma unroll
    for (int j = 0; j < 8; j++) wbase += (j < w) ? wsum[j] : 0;

    int excl = (ps - s) + wbase + sBase;
    int r[8];
#pragma unroll
    for (int i = 0; i < 8; i++) { r[i] = excl; excl += v[i]; }
    if (vec) {
        *reinterpret_cast<int4*>(g_roff + beg)       = make_int4(r[0], r[1], r[2], r[3]);
        *reinterpret_cast<int4*>(g_roff + beg + 4)   = make_int4(r[4], r[5], r[6], r[7]);
        *reinterpret_cast<int4*>(g_cursor + beg)     = make_int4(r[0], r[1], r[2], r[3]);
        *reinterpret_cast<int4*>(g_cursor + beg + 4) = make_int4(r[4], r[5], r[6], r[7]);
    } else {
#pragma unroll
        for (int i = 0; i < 8; i++) {
            int idx = beg + i;
            if (idx < N) { g_roff[idx] = r[i]; g_cursor[idx] = r[i]; }
        }
    }
}

// scatter to CSR + fused layer-0 softmax-denominator sums
__global__ void __launch_bounds__(256) scatter_sum_kernel(
    const int* __restrict__ ei32, int E, int N)
{
    int is32 = block_detect_is32(ei32);
    int e = blockIdx.x * blockDim.x + threadIdx.x;
    int ET = E + N;
    float s0 = 0.f, s1 = 0.f;
    if (e < ET) {
        int s, d;
        if (e < E) load_edge(ei32, e, E, is32, s, d);
        else       s = d = e - E;
        int pos = atomicAdd(&g_cursor[d], 1);
        g_csr[pos] = s;
        s0 = lrexp(g_sdst[d * 2]     + g_ssrc[s * 2]);
        s1 = lrexp(g_sdst[d * 2 + 1] + g_ssrc[s * 2 + 1]);
    }
#pragma unroll
    for (int o = 16; o > 0; o >>= 1) {
        s0 += __shfl_xor_sync(0xffffffffu, s0, o);
        s1 += __shfl_xor_sync(0xffffffffu, s1, o);
    }
    __shared__ float sm0[8], sm1[8];
    if ((threadIdx.x & 31) == 0) {
        sm0[threadIdx.x >> 5] = s0;
        sm1[threadIdx.x >> 5] = s1;
    }
    __syncthreads();
    if (threadIdx.x == 0) {
        float t0 = 0.f, t1 = 0.f;
#pragma unroll
        for (int i = 0; i < 8; i++) { t0 += sm0[i]; t1 += sm1[i]; }
        atomicAdd(&g_sum[0], t0);
        atomicAdd(&g_sum[1], t1);
    }
}

// layer-2 softmax-denominator sums only
__global__ void __launch_bounds__(256) sum2_kernel(
    const int* __restrict__ ei32, int E, int N)
{
    int is32 = block_detect_is32(ei32);
    int e = blockIdx.x * blockDim.x + threadIdx.x;
    int ET = E + N;
    float s0 = 0.f, s1 = 0.f;
    if (e < ET) {
        int s, d;
        if (e < E) load_edge(ei32, e, E, is32, s, d);
        else       s = d = e - E;
        s0 = lrexp(g_sdst[d * 2]     + g_ssrc[s * 2]);
        s1 = lrexp(g_sdst[d * 2 + 1] + g_ssrc[s * 2 + 1]);
    }
#pragma unroll
    for (int o = 16; o > 0; o >>= 1) {
        s0 += __shfl_xor_sync(0xffffffffu, s0, o);
        s1 += __shfl_xor_sync(0xffffffffu, s1, o);
    }
    __shared__ float sm0[8], sm1[8];
    if ((threadIdx.x & 31) == 0) {
        sm0[threadIdx.x >> 5] = s0;
        sm1[threadIdx.x >> 5] = s1;
    }
    __syncthreads();
    if (threadIdx.x == 0) {
        float t0 = 0.f, t1 = 0.f;
#pragma unroll
        for (int i = 0; i < 8; i++) { t0 += sm0[i]; t1 += sm1[i]; }
        atomicAdd(&g_sum[2], t0);
        atomicAdd(&g_sum[3], t1);
    }
}

// ---------------- gather: warp per dst, 2 edges/iter, uint4 fp16 loads ------
// Lane layout: sub = lane>>4 selects edge (j or j+1); g = lane&15 covers
// halves 8g..8g+7 of the src row (g<8: head0, g>=8: head1).
__global__ void __launch_bounds__(256) gather_kernel(
    int N, int layer, float* __restrict__ outp0,
    const float* __restrict__ bias, int doRelu, int toAcc)
{
    int wid  = (blockIdx.x * blockDim.x + threadIdx.x) >> 5;
    int lane = threadIdx.x & 31;
    if (wid >= N) return;
    int d = wid;

    float* outp = toAcc ? g_acc : outp0;

    int beg = g_roff[d];
    int end = g_roff[d + 1];

    float inv0 = 0.5f * HSCALE_INV / (g_sum[layer * 2]     + 1e-10f);
    float inv1 = 0.5f * HSCALE_INV / (g_sum[layer * 2 + 1] + 1e-10f);

    float2 scd = *reinterpret_cast<const float2*>(g_sdst + d * 2);

    int g   = lane & 15;
    int sub = lane >> 4;
    bool isH1 = (g >= 8);

    const uint4* hv = reinterpret_cast<const uint4*>(g_hh);  // 16 uint4 per row
    float acc[8];
#pragma unroll
    for (int i = 0; i < 8; i++) acc[i] = 0.f;

    for (int base = beg; base < end; base += 32) {
        int idx = base + lane;
        int   s   = 0;
        float aw0 = 0.f, aw1 = 0.f;
        if (idx < end) {
            s = g_csr[idx];
            float2 scs = *reinterpret_cast<const float2*>(g_ssrc + s * 2);
            aw0 = lrexp(scd.x + scs.x) * inv0;
            aw1 = lrexp(scd.y + scs.y) * inv1;
        }
        int cnt = min(32, end - base);
#pragma unroll 4
        for (int j = 0; j < cnt; j += 2) {
            int jj = j + sub;                       // may be == cnt on odd tail
            int   sj = __shfl_sync(0xffffffffu, s,   jj & 31);
            float w0 = __shfl_sync(0xffffffffu, aw0, jj & 31);
            float w1 = __shfl_sync(0xffffffffu, aw1, jj & 31);
            float ww = isH1 ? w1 : w0;
            if (jj >= cnt) ww = 0.f;                // tail edge: zero weight, safe read
            uint4 raw = hv[(size_t)sj * 16 + g];    // 8 halves
            float2 f0 = __half22float2(*reinterpret_cast<__half2*>(&raw.x));
            float2 f1 = __half22float2(*reinterpret_cast<__half2*>(&raw.y));
            float2 f2 = __half22float2(*reinterpret_cast<__half2*>(&raw.z));
            float2 f3 = __half22float2(*reinterpret_cast<__half2*>(&raw.w));
            acc[0] = fmaf(ww, f0.x, acc[0]);
            acc[1] = fmaf(ww, f0.y, acc[1]);
            acc[2] = fmaf(ww, f1.x, acc[2]);
            acc[3] = fmaf(ww, f1.y, acc[3]);
            acc[4] = fmaf(ww, f2.x, acc[4]);
            acc[5] = fmaf(ww, f2.y, acc[5]);
            acc[6] = fmaf(ww, f3.x, acc[6]);
            acc[7] = fmaf(ww, f3.y, acc[7]);
        }
    }

    // combine edge pair (xor 16), then heads (xor 8): lanes 0-7 hold 8 channels
#pragma unroll
    for (int i = 0; i < 8; i++) {
        acc[i] += __shfl_xor_sync(0xffffffffu, acc[i], 16);
        acc[i] += __shfl_xor_sync(0xffffffffu, acc[i], 8);
    }

    if (lane < 8) {
        const float4* bv = reinterpret_cast<const float4*>(bias);
        float4 b0 = bv[lane * 2], b1 = bv[lane * 2 + 1];
        float4 o0 = make_float4(acc[0] + b0.x, acc[1] + b0.y, acc[2] + b0.z, acc[3] + b0.w);
        float4 o1 = make_float4(acc[4] + b1.x, acc[5] + b1.y, acc[6] + b1.z, acc[7] + b1.w);
        if (doRelu) {
            o0.x = fmaxf(o0.x, 0.f); o0.y = fmaxf(o0.y, 0.f);
            o0.z = fmaxf(o0.z, 0.f); o0.w = fmaxf(o0.w, 0.f);
            o1.x = fmaxf(o1.x, 0.f); o1.y = fmaxf(o1.y, 0.f);
            o1.z = fmaxf(o1.z, 0.f); o1.w = fmaxf(o1.w, 0.f);
        }
        float* dst = outp + (size_t)d * CD + lane * 8;
        *reinterpret_cast<float4*>(dst)     = o0;
        *reinterpret_cast<float4*>(dst + 4) = o1;
    }
}

// ---------------- launch ----------------
extern "C" void kernel_launch(void* const* d_in, const int* in_sizes, int n_in,
                              void* d_out, int out_size)
{
    const float* x    = (const float*)d_in[0];
    const int*   ei32 = (const int*)d_in[1];
    const float* W1   = (const float*)d_in[2];
    const float* att1 = (const float*)d_in[3];
    const float* b1   = (const float*)d_in[4];
    const float* W2   = (const float*)d_in[5];
    const float* att2 = (const float*)d_in[6];
    const float* b2   = (const float*)d_in[7];
    float* out = (float*)d_out;

    int N  = in_sizes[0] / FIN;
    int E  = in_sizes[1] / 2;
    int ET = E + N;
    int nb = (N + SCAN_CHUNK - 1) / SCAN_CHUNK;

    int gemmBlocks = (N + 127) / 128;
    int histBlocks = (E + 255) / 256;

    // 1: GEMM1 + degree histogram fused (independent block ranges)
    gemm_tc_kernel<FIN><<<gemmBlocks + histBlocks, 256>>>(
        x, 0, W1, att1, N, ei32, E, gemmBlocks);
    partial_kernel<<<nb, 256>>>(N);                                     // 2
    offsets_kernel<<<nb, 256>>>(N, nb);                                 // 3
    scatter_sum_kernel<<<(ET + 255) / 256, 256>>>(ei32, E, N);          // 4
    gather_kernel<<<(N * 32 + 255) / 256, 256>>>(N, 0, out, b1, 1, 1);  // 5
    gemm_tc_kernel<CD><<<gemmBlocks, 256>>>(
        x /*unused*/, 1, W2, att2, N, ei32, 0, gemmBlocks);             // 6
    sum2_kernel<<<(ET + 255) / 256, 256>>>(ei32, E, N);                 // 7
    gather_kernel<<<(N * 32 + 255) / 256, 256>>>(N, 1, out, b2, 0, 0);  // 8
}

// round 11
// speedup vs baseline: 2.9420x; 1.0747x over previous
#include <cuda_runtime.h>
#include <cuda_fp16.h>
#include <math.h>

// Problem constants (shapes fixed by the dataset)
#define HC   128      // HEADS * C
#define CD   64       // C
#define FIN  128      // Fin of layer 1
#define NMAX 50048
#define EMAX 800256
#define ETMAX (NMAX + EMAX)
#define SCAN_CHUNK 2048   // elements per scan block (256 thr x 8)
#define HSCALE 4096.0f    // fp16 storage scale (keeps layer-2 h out of subnormals)
#define HSCALE_INV (1.0f / 4096.0f)

// ---------------- scratch (device globals; no allocation) ----------------
__device__ __align__(16) __half g_hh[(size_t)NMAX * HC];    // GEMM output * HSCALE, fp16
__device__ __align__(16) float  g_tmp[(size_t)NMAX * HC];   // raw gather acc [N,2,64] fp32
__device__ __align__(8)  float  g_sdst[NMAX * 2];           // per-node dst-scores [N,H]
__device__ __align__(8)  float  g_ssrc[NMAX * 2];           // per-node src-scores [N,H]
__device__ float    g_sum[4];                   // per-layer per-head exp sums
// CSR: g_deg stores EXTRA in-degree (self-loop excluded); zero-init and
// reset-after-use by offsets_kernel -> replay-clean with no init pass.
__device__ __align__(16) int g_deg[NMAX];
__device__ __align__(16) int g_roff[NMAX + 8];
__device__ __align__(16) int g_cursor[NMAX];
__device__ int      g_csr[ETMAX];               // src per incoming edge (dst-sorted)
__device__ int      g_bsum[256];                // per-block degree sums

__device__ __forceinline__ unsigned f2tf32(float f) {
    unsigned r;
    asm("cvt.rna.tf32.f32 %0, %1;" : "=r"(r) : "f"(f));
    return r;
}

__device__ __forceinline__ void mma_tf32(
    float& c0, float& c1, float& c2, float& c3,
    unsigned a0, unsigned a1, unsigned a2, unsigned a3,
    unsigned b0, unsigned b1)
{
    asm volatile(
        "mma.sync.aligned.m16n8k8.row.col.f32.tf32.tf32.f32 "
        "{%0,%1,%2,%3}, {%4,%5,%6,%7}, {%8,%9}, {%0,%1,%2,%3};"
        : "+f"(c0), "+f"(c1), "+f"(c2), "+f"(c3)
        : "r"(a0), "r"(a1), "r"(a2), "r"(a3), "r"(b0), "r"(b1));
}

// per-block dtype detection: int64 edges (<2^31) have all-zero odd words.
__device__ __forceinline__ int block_detect_is32(const int* __restrict__ ei32) {
    __shared__ int sIs32;
    if (threadIdx.x == 0) {
        unsigned v = 0;
#pragma unroll
        for (int i = 0; i < 32; i++) v |= (unsigned)ei32[2 * i + 1];
        sIs32 = (v != 0u) ? 1 : 0;
    }
    __syncthreads();
    return sIs32;
}

__device__ __forceinline__ void load_edge(const int* __restrict__ ei32,
                                          int e, int E, int is32, int& s, int& d) {
    if (is32) { s = ei32[e];     d = ei32[E + e]; }
    else      { s = ei32[2 * e]; d = ei32[2 * (E + e)]; }
}

__device__ __forceinline__ float lrexp(float a) {
    a = (a >= 0.f) ? a : 0.2f * a;
    return __expf(a);
}

// ---------------- tf32 tensor-core GEMM + fused score epilogue --------------
// Blocks [0, nGemm): GEMM. Blocks >= nGemm: degree histogram (layer 1 only).
// fromTmp=1 (layer 2): loader reads g_tmp and applies layer-1 normalization
// (inv from g_sum[0,1]) + bias + relu on the fly.
#define TP 36   // smem pitch (32 k + 4 pad) -> conflict-free fragment loads

template <int K>
__global__ void __launch_bounds__(256) gemm_tc_kernel(
    const float* __restrict__ X0, int fromTmp, const float* __restrict__ bias1,
    const float* __restrict__ W, const float* __restrict__ att, int N,
    const int* __restrict__ ei32, int nHistE, int nGemm)
{
    // ---- histogram part (layer-1 launch only) ----
    if (blockIdx.x >= (unsigned)nGemm) {
        int hb = blockIdx.x - nGemm;
        int is32 = block_detect_is32(ei32);
        if (hb == 0 && threadIdx.x < 4) g_sum[threadIdx.x] = 0.f;
        int e = hb * 256 + threadIdx.x;
        if (e < nHistE) {
            int s, d;
            load_edge(ei32, e, nHistE, is32, s, d);
            atomicAdd(&g_deg[d], 1);
        }
        return;
    }

    __shared__ __align__(16) unsigned sX[128 * TP];
    __shared__ __align__(16) unsigned sW[128 * TP];
    __shared__ float sAtt[256];

    int t    = threadIdx.x;
    int wid  = t >> 5;
    int lane = t & 31;
    int gid  = lane >> 2;
    int tid  = lane & 3;
    int wm   = wid & 3;
    int wn   = wid >> 2;    // head
    int row0 = blockIdx.x * 128;
    int wrow = wm * 32;
    int wcol = wn * 64;

    if (t < 256) sAtt[t] = att[t];

    float inv0 = 0.f, inv1 = 0.f;
    if (fromTmp) {
        inv0 = 0.5f * HSCALE_INV / (g_sum[0] + 1e-10f);
        inv1 = 0.5f * HSCALE_INV / (g_sum[1] + 1e-10f);
    }

    float c[2][8][4];
#pragma unroll
    for (int mt = 0; mt < 2; mt++)
#pragma unroll
        for (int nt = 0; nt < 8; nt++)
#pragma unroll
            for (int i = 0; i < 4; i++) c[mt][nt][i] = 0.f;

    for (int kc = 0; kc < K; kc += 32) {
#pragma unroll
        for (int it = 0; it < 4; it++) {
            int idx = t + it * 256;
            int r = idx >> 3;
            int q = idx & 7;
            int k = q * 4;

            float4 v = make_float4(0.f, 0.f, 0.f, 0.f);
            int grow = row0 + r;
            if (grow < N) {
                if (fromTmp) {
                    // layer-1 output = relu(tmp0*inv0 + tmp1*inv1 + b1)
                    int qi = (kc + k) >> 2;   // float4 index in [0,16)
                    const float4* t4 = reinterpret_cast<const float4*>(g_tmp)
                                       + (size_t)grow * 32;
                    float4 t0 = t4[qi], t1 = t4[qi + 16];
                    float4 bb = reinterpret_cast<const float4*>(bias1)[qi];
                    v.x = fmaxf(fmaf(t0.x, inv0, fmaf(t1.x, inv1, bb.x)), 0.f);
                    v.y = fmaxf(fmaf(t0.y, inv0, fmaf(t1.y, inv1, bb.y)), 0.f);
                    v.z = fmaxf(fmaf(t0.z, inv0, fmaf(t1.z, inv1, bb.z)), 0.f);
                    v.w = fmaxf(fmaf(t0.w, inv0, fmaf(t1.w, inv1, bb.w)), 0.f);
                } else {
                    v = *reinterpret_cast<const float4*>(X0 + (size_t)grow * K + kc + k);
                }
            }
            uint4 tv = make_uint4(f2tf32(v.x), f2tf32(v.y), f2tf32(v.z), f2tf32(v.w));
            *reinterpret_cast<uint4*>(&sX[r * TP + k]) = tv;

            float4 w = *reinterpret_cast<const float4*>(W + (size_t)r * K + kc + k);
            uint4 tw = make_uint4(f2tf32(w.x), f2tf32(w.y), f2tf32(w.z), f2tf32(w.w));
            *reinterpret_cast<uint4*>(&sW[r * TP + k]) = tw;
        }
        __syncthreads();

#pragma unroll
        for (int ks = 0; ks < 4; ks++) {
            int k0 = ks * 8;
            unsigned a[2][4];
#pragma unroll
            for (int mt = 0; mt < 2; mt++) {
                int r = wrow + mt * 16 + gid;
                a[mt][0] = sX[r * TP + k0 + tid];
                a[mt][1] = sX[(r + 8) * TP + k0 + tid];
                a[mt][2] = sX[r * TP + k0 + tid + 4];
                a[mt][3] = sX[(r + 8) * TP + k0 + tid + 4];
            }
            unsigned b[8][2];
#pragma unroll
            for (int nt = 0; nt < 8; nt++) {
                int n = wcol + nt * 8 + gid;
                b[nt][0] = sW[n * TP + k0 + tid];
                b[nt][1] = sW[n * TP + k0 + tid + 4];
            }
#pragma unroll
            for (int mt = 0; mt < 2; mt++)
#pragma unroll
                for (int nt = 0; nt < 8; nt++)
                    mma_tf32(c[mt][nt][0], c[mt][nt][1], c[mt][nt][2], c[mt][nt][3],
                             a[mt][0], a[mt][1], a[mt][2], a[mt][3],
                             b[nt][0], b[nt][1]);
        }
        __syncthreads();
    }

    float dp[2][2] = {{0.f, 0.f}, {0.f, 0.f}};
    float sp[2][2] = {{0.f, 0.f}, {0.f, 0.f}};

#pragma unroll
    for (int mt = 0; mt < 2; mt++) {
        int rlo = row0 + wrow + mt * 16 + gid;
        int rhi = rlo + 8;
#pragma unroll
        for (int nt = 0; nt < 8; nt++) {
            int cw = nt * 8 + tid * 2;
            int gc = wcol + cw;
            float c0 = c[mt][nt][0], c1 = c[mt][nt][1];
            float c2 = c[mt][nt][2], c3 = c[mt][nt][3];
            if (rlo < N)
                *reinterpret_cast<__half2*>(g_hh + (size_t)rlo * HC + gc) =
                    __floats2half2_rn(c0 * HSCALE, c1 * HSCALE);
            if (rhi < N)
                *reinterpret_cast<__half2*>(g_hh + (size_t)rhi * HC + gc) =
                    __floats2half2_rn(c2 * HSCALE, c3 * HSCALE);

            float ad0 = sAtt[wn * 128 + cw],      ad1 = sAtt[wn * 128 + cw + 1];
            float as0 = sAtt[wn * 128 + 64 + cw], as1 = sAtt[wn * 128 + 64 + cw + 1];
            dp[mt][0] = fmaf(c0, ad0, fmaf(c1, ad1, dp[mt][0]));
            sp[mt][0] = fmaf(c0, as0, fmaf(c1, as1, sp[mt][0]));
            dp[mt][1] = fmaf(c2, ad0, fmaf(c3, ad1, dp[mt][1]));
            sp[mt][1] = fmaf(c2, as0, fmaf(c3, as1, sp[mt][1]));
        }
    }
#pragma unroll
    for (int mt = 0; mt < 2; mt++)
#pragma unroll
        for (int u = 0; u < 2; u++) {
#pragma unroll
            for (int o = 1; o <= 2; o <<= 1) {
                dp[mt][u] += __shfl_xor_sync(0xffffffffu, dp[mt][u], o);
                sp[mt][u] += __shfl_xor_sync(0xffffffffu, sp[mt][u], o);
            }
            if (tid == 0) {
                int row = row0 + wrow + mt * 16 + gid + u * 8;
                if (row < N) {
                    g_sdst[row * 2 + wn] = dp[mt][u];
                    g_ssrc[row * 2 + wn] = sp[mt][u];
                }
            }
        }
}

// ---------------- scan phase 1: per-block sums (vectorized, warp reduce) ----
__global__ void __launch_bounds__(256) partial_kernel(int N) {
    int b = blockIdx.x, t = threadIdx.x;
    int beg = b * SCAN_CHUNK + t * 8;
    int s = 0;
    if (beg + 8 <= N) {
        int4 a = *reinterpret_cast<const int4*>(g_deg + beg);
        int4 c = *reinterpret_cast<const int4*>(g_deg + beg + 4);
        s = a.x + a.y + a.z + a.w + c.x + c.y + c.z + c.w + 8;
    } else {
#pragma unroll
        for (int i = 0; i < 8; i++) {
            int idx = beg + i;
            if (idx < N) s += g_deg[idx] + 1;
        }
    }
    s = __reduce_add_sync(0xffffffffu, s);
    __shared__ int wsum[8];
    if ((t & 31) == 0) wsum[t >> 5] = s;
    __syncthreads();
    if (t == 0) {
        int tot = 0;
#pragma unroll
        for (int i = 0; i < 8; i++) tot += wsum[i];
        g_bsum[b] = tot;
    }
}

// ---------------- scan phase 2: offsets (warp-shuffle scan, vectorized) -----
__global__ void __launch_bounds__(256) offsets_kernel(int N, int nb) {
    __shared__ int sBase;
    __shared__ int wsum[8];
    int b = blockIdx.x, t = threadIdx.x;
    int lane = t & 31, w = t >> 5;

    if (t < 32) {
        int val = (t < nb) ? g_bsum[t] : 0;
        int base = __reduce_add_sync(0xffffffffu, (t < b) ? val : 0);
        if (t == 0) sBase = base;
        if (b == 0) {
            int total = __reduce_add_sync(0xffffffffu, val);
            if (t == 0) g_roff[N] = total;
        }
    }

    int beg = b * SCAN_CHUNK + t * 8;
    int v[8];
    int s;
    bool vec = (beg + 8 <= N);
    if (vec) {
        int4 a = *reinterpret_cast<const int4*>(g_deg + beg);
        int4 c = *reinterpret_cast<const int4*>(g_deg + beg + 4);
        v[0] = a.x + 1; v[1] = a.y + 1; v[2] = a.z + 1; v[3] = a.w + 1;
        v[4] = c.x + 1; v[5] = c.y + 1; v[6] = c.z + 1; v[7] = c.w + 1;
        int4 z = make_int4(0, 0, 0, 0);
        *reinterpret_cast<int4*>(g_deg + beg)     = z;
        *reinterpret_cast<int4*>(g_deg + beg + 4) = z;
    } else {
#pragma unroll
        for (int i = 0; i < 8; i++) {
            int idx = beg + i;
            v[i] = (idx < N) ? (g_deg[idx] + 1) : 0;
            if (idx < N) g_deg[idx] = 0;
        }
    }
    s = v[0] + v[1] + v[2] + v[3] + v[4] + v[5] + v[6] + v[7];

    int ps = s;
#pragma unroll
    for (int o = 1; o < 32; o <<= 1) {
        int x = __shfl_up_sync(0xffffffffu, ps, o);
        if (lane >= o) ps += x;
    }
    if (lane == 31) wsum[w] = ps;
    __syncthreads();
    int wbase = 0;
#pragma unroll
    for (int j = 0; j < 8; j++) wbase += (j < w) ? wsum[j] : 0;

    int excl = (ps - s) + wbase + sBase;
    int r[8];
#pragma unroll
    for (int i = 0; i < 8; i++) { r[i] = excl; excl += v[i]; }
    if (vec) {
        *reinterpret_cast<int4*>(g_roff + beg)       = make_int4(r[0], r[1], r[2], r[3]);
        *reinterpret_cast<int4*>(g_roff + beg + 4)   = make_int4(r[4], r[5], r[6], r[7]);
        *reinterpret_cast<int4*>(g_cursor + beg)     = make_int4(r[0], r[1], r[2], r[3]);
        *reinterpret_cast<int4*>(g_cursor + beg + 4) = make_int4(r[4], r[5], r[6], r[7]);
    } else {
#pragma unroll
        for (int i = 0; i < 8; i++) {
            int idx = beg + i;
            if (idx < N) { g_roff[idx] = r[i]; g_cursor[idx] = r[i]; }
        }
    }
}

// ---------------- scatter: pure CSR build (no sums) --------------------------
__global__ void __launch_bounds__(256) scatter_kernel(
    const int* __restrict__ ei32, int E, int N)
{
    int is32 = block_detect_is32(ei32);
    int e = blockIdx.x * blockDim.x + threadIdx.x;
    int ET = E + N;
    if (e >= ET) return;
    int s, d;
    if (e < E) load_edge(ei32, e, E, is32, s, d);
    else       s = d = e - E;
    int pos = atomicAdd(&g_cursor[d], 1);
    g_csr[pos] = s;
}

// ---------------- gather: raw (unnormalized) acc + fused denominator sums ----
// Writes tmp[d][128] = sum_e exp(..)*h_scaled (head-separated) and
// atomically accumulates per-head exp-sums into g_sum[2*layer..].
__global__ void __launch_bounds__(256) gather_kernel(int N, int layer)
{
    int wid  = (blockIdx.x * blockDim.x + threadIdx.x) >> 5;
    int lane = threadIdx.x & 31;
    int wIdx = threadIdx.x >> 5;
    bool active = (wid < N);
    int d = active ? wid : 0;

    int g   = lane & 15;
    int sub = lane >> 4;
    bool isH1 = (g >= 8);

    const uint4* hv = reinterpret_cast<const uint4*>(g_hh);
    float acc[8];
#pragma unroll
    for (int i = 0; i < 8; i++) acc[i] = 0.f;
    float ws0 = 0.f, ws1 = 0.f;

    if (active) {
        int beg = g_roff[d];
        int end = g_roff[d + 1];
        float2 scd = *reinterpret_cast<const float2*>(g_sdst + d * 2);

        for (int base = beg; base < end; base += 32) {
            int idx = base + lane;
            int   s   = 0;
            float aw0 = 0.f, aw1 = 0.f;
            if (idx < end) {
                s = g_csr[idx];
                float2 scs = *reinterpret_cast<const float2*>(g_ssrc + s * 2);
                aw0 = lrexp(scd.x + scs.x);
                aw1 = lrexp(scd.y + scs.y);
                ws0 += aw0;
                ws1 += aw1;
            }
            int cnt = min(32, end - base);
#pragma unroll 4
            for (int j = 0; j < cnt; j += 2) {
                int jj = j + sub;
                int   sj = __shfl_sync(0xffffffffu, s,   jj & 31);
                float w0 = __shfl_sync(0xffffffffu, aw0, jj & 31);
                float w1 = __shfl_sync(0xffffffffu, aw1, jj & 31);
                float ww = isH1 ? w1 : w0;
                if (jj >= cnt) ww = 0.f;
                uint4 raw = hv[(size_t)sj * 16 + g];
                float2 f0 = __half22float2(*reinterpret_cast<__half2*>(&raw.x));
                float2 f1 = __half22float2(*reinterpret_cast<__half2*>(&raw.y));
                float2 f2 = __half22float2(*reinterpret_cast<__half2*>(&raw.z));
                float2 f3 = __half22float2(*reinterpret_cast<__half2*>(&raw.w));
                acc[0] = fmaf(ww, f0.x, acc[0]);
                acc[1] = fmaf(ww, f0.y, acc[1]);
                acc[2] = fmaf(ww, f1.x, acc[2]);
                acc[3] = fmaf(ww, f1.y, acc[3]);
                acc[4] = fmaf(ww, f2.x, acc[4]);
                acc[5] = fmaf(ww, f2.y, acc[5]);
                acc[6] = fmaf(ww, f3.x, acc[6]);
                acc[7] = fmaf(ww, f3.y, acc[7]);
            }
        }
    }

    // edge-pair reduce (xor 16); lanes 0-15 hold the 128 channels head-separated
#pragma unroll
    for (int i = 0; i < 8; i++)
        acc[i] += __shfl_xor_sync(0xffffffffu, acc[i], 16);

    if (active && lane < 16) {
        float* dst = g_tmp + (size_t)d * HC + g * 8;
        *reinterpret_cast<float4*>(dst)     = make_float4(acc[0], acc[1], acc[2], acc[3]);
        *reinterpret_cast<float4*>(dst + 4) = make_float4(acc[4], acc[5], acc[6], acc[7]);
    }

    // block-reduce exp sums -> 2 atomics per block
#pragma unroll
    for (int o = 16; o > 0; o >>= 1) {
        ws0 += __shfl_xor_sync(0xffffffffu, ws0, o);
        ws1 += __shfl_xor_sync(0xffffffffu, ws1, o);
    }
    __shared__ float sm0[8], sm1[8];
    if (lane == 0) { sm0[wIdx] = ws0; sm1[wIdx] = ws1; }
    __syncthreads();
    if (threadIdx.x == 0) {
        float t0 = 0.f, t1 = 0.f;
#pragma unroll
        for (int i = 0; i < 8; i++) { t0 += sm0[i]; t1 += sm1[i]; }
        atomicAdd(&g_sum[layer * 2],     t0);
        atomicAdd(&g_sum[layer * 2 + 1], t1);
    }
}

// ---------------- finalize: out = tmp0*inv0 + tmp1*inv1 + b2 -----------------
__global__ void __launch_bounds__(256) finalize_kernel(
    int N, float* __restrict__ out, const float* __restrict__ bias)
{
    int i = blockIdx.x * blockDim.x + threadIdx.x;
    if (i >= N * 16) return;
    int d = i >> 4, q = i & 15;
    float inv0 = 0.5f * HSCALE_INV / (g_sum[2] + 1e-10f);
    float inv1 = 0.5f * HSCALE_INV / (g_sum[3] + 1e-10f);
    const float4* t4 = reinterpret_cast<const float4*>(g_tmp) + (size_t)d * 32;
    float4 t0 = t4[q], t1 = t4[q + 16];
    float4 b  = reinterpret_cast<const float4*>(bias)[q];
    float4 o;
    o.x = fmaf(t0.x, inv0, fmaf(t1.x, inv1, b.x));
    o.y = fmaf(t0.y, inv0, fmaf(t1.y, inv1, b.y));
    o.z = fmaf(t0.z, inv0, fmaf(t1.z, inv1, b.z));
    o.w = fmaf(t0.w, inv0, fmaf(t1.w, inv1, b.w));
    reinterpret_cast<float4*>(out)[i] = o;
}

// ---------------- launch ----------------
extern "C" void kernel_launch(void* const* d_in, const int* in_sizes, int n_in,
                              void* d_out, int out_size)
{
    const float* x    = (const float*)d_in[0];
    const int*   ei32 = (const int*)d_in[1];
    const float* W1   = (const float*)d_in[2];
    const float* att1 = (const float*)d_in[3];
    const float* b1   = (const float*)d_in[4];
    const float* W2   = (const float*)d_in[5];
    const float* att2 = (const float*)d_in[6];
    const float* b2   = (const float*)d_in[7];
    float* out = (float*)d_out;

    int N  = in_sizes[0] / FIN;
    int E  = in_sizes[1] / 2;
    int ET = E + N;
    int nb = (N + SCAN_CHUNK - 1) / SCAN_CHUNK;

    int gemmBlocks = (N + 127) / 128;
    int histBlocks = (E + 255) / 256;

    // 1: GEMM1 + degree histogram fused
    gemm_tc_kernel<FIN><<<gemmBlocks + histBlocks, 256>>>(
        x, 0, nullptr, W1, att1, N, ei32, E, gemmBlocks);
    partial_kernel<<<nb, 256>>>(N);                                     // 2
    offsets_kernel<<<nb, 256>>>(N, nb);                                 // 3
    scatter_kernel<<<(ET + 255) / 256, 256>>>(ei32, E, N);              // 4
    gather_kernel<<<(N * 32 + 255) / 256, 256>>>(N, 0);                 // 5
    // 6: GEMM2 with fused layer-1 normalization + bias + relu in the loader
    gemm_tc_kernel<CD><<<gemmBlocks, 256>>>(
        x, 1, b1, W2, att2, N, ei32, 0, gemmBlocks);
    gather_kernel<<<(N * 32 + 255) / 256, 256>>>(N, 1);                 // 7
    finalize_kernel<<<(N * 16 + 255) / 256, 256>>>(N, out, b2);         // 8
}